// round 3
// baseline (speedup 1.0000x reference)
#include <cuda_runtime.h>
#include <math.h>

#define PI 3.14159265358979323846

#define BATCH 8
#define NPTS  1024
#define F0    100
#define F1    100
#define NCLS  40

#define NA60  60    // 2*B_IN
#define L1MAX 16    // B_MID
#define N32   32    // 2*B_MID
#define L2MAX 10    // B_OUT
#define N20   20    // 2*B_OUT

#define NC1   256   // sum_{l<16}(2l+1) = 16^2
#define NSQ1  5456  // sum_{l<16}(2l+1)^2
#define NSQ2  1330  // sum_{l<10}(2l+1)^2
#define MR1   31    // 2*15+1
#define MR2   19    // 2*9+1

__device__ __forceinline__ int offsq(int l){ return l*(4*l*l-1)/3; }

// ---------------- scratch buffers (static device globals) ----------------
__device__ float  g_img[BATCH*NA60*NA60];
__device__ float2 g_Ga [BATCH*NA60*MR1];
__device__ float2 g_X1 [BATCH*NC1];
__device__ float2 g_Wh1[F0*MR1];
__device__ float2 g_Y1 [F0*NC1];
__device__ float  g_h1 [BATCH*F0*N32*N32*N32];       // 104.9 MB
__device__ float  g_bn1a[F0], g_bn1bv[F0];
__device__ float2 g_G2 [BATCH*F0*N32*MR2*MR2];       // 73.9 MB
__device__ float2 g_X2 [BATCH*F0*NSQ2];
__device__ float2 g_Wh2[F0*F1*MR2];
__device__ float2 g_Aa [BATCH*F0*NSQ2];
__device__ float2 g_Z2 [BATCH*F1*NSQ2];
__device__ float  g_h2 [BATCH*F1*N20*N20*N20];       // 25.6 MB
__device__ float  g_bn2a[F1], g_bn2bv[F1];
__device__ float  g_feat[BATCH*F1];

// ---------------- wigner / quadrature tables ----------------
__device__ float g_d16   [N32*NSQ1];   // full d^l at dh(16) betas, l<16 (prefix p<1330 == l<10 table)
__device__ float g_d10   [N20*NSQ2];   // full d^l at dh(10) betas, l<10
__device__ float g_dcol30[NA60*NC1];   // d^l_{m,0} at dh(30) betas, l<16
__device__ float g_dhcol [NC1];        // d^l_{m,0}(pi/2), l<16
__device__ float g_dh10  [NSQ2];       // full d^l(pi/2), l<10
__device__ float g_qw30[NA60], g_qw16[N32], g_qw10[N20];

// ================= setup: wigner-d via factorial sum (double) =================
__device__ double d_ipow(double x, int n){ double r=1.0; for(int i=0;i<n;i++) r*=x; return r; }

__device__ double d_wig(int l, int mp, int m, double beta){
    if (l == 0) return 1.0;
    double f[36]; f[0]=1.0;
    for (int i=1;i<36;i++) f[i]=f[i-1]*(double)i;
    double cb = cos(0.5*beta), sb = sin(0.5*beta);
    int smin = max(0, m-mp);
    int smax = min(l+m, l-mp);
    double pref = sqrt(f[l+mp]*f[l-mp]*f[l+m]*f[l-m]);
    double acc = 0.0;
    for (int s=smin; s<=smax; s++){
        double v = d_ipow(cb, 2*l+m-mp-2*s) * d_ipow(sb, mp-m+2*s)
                 / (f[l+m-s]*f[s]*f[mp-m+s]*f[l-mp-s]);
        acc += ((mp-m+s)&1) ? -v : v;
    }
    return pref*acc;
}

__global__ void k_wig_full(int which){
    int bgrid, Lmax, halfpi=0; float* out;
    if (which==0){ bgrid=16; Lmax=16; out=g_d16; }
    else if (which==1){ bgrid=10; Lmax=10; out=g_d10; }
    else { bgrid=1; Lmax=10; out=g_dh10; halfpi=1; }
    int per = Lmax*(4*Lmax*Lmax-1)/3;
    int nbeta = halfpi ? 1 : 2*bgrid;
    int tid = blockIdx.x*blockDim.x + threadIdx.x;
    if (tid >= nbeta*per) return;
    int k = tid/per, p = tid%per;
    int l=0; while (p >= (2*l+1)*(2*l+1)){ p -= (2*l+1)*(2*l+1); l++; }
    int jm = p/(2*l+1), jn = p%(2*l+1);
    double beta = halfpi ? 0.5*PI : PI*(2*k+1)/(4.0*bgrid);
    out[tid] = (float)d_wig(l, jm-l, jn-l, beta);
}

__global__ void k_wig_col(int which){
    int bgrid, halfpi=0; float* out;
    if (which==0){ bgrid=30; out=g_dcol30; }
    else { bgrid=1; out=g_dhcol; halfpi=1; }
    int per = NC1;
    int nbeta = halfpi ? 1 : 2*bgrid;
    int tid = blockIdx.x*blockDim.x + threadIdx.x;
    if (tid >= nbeta*per) return;
    int k = tid/per, p = tid%per;
    int l=0; while ((l+1)*(l+1) <= p) l++;
    int jm = p - l*l;
    double beta = halfpi ? 0.5*PI : PI*(2*k+1)/(4.0*bgrid);
    out[tid] = (float)d_wig(l, jm-l, 0, beta);
}

__global__ void k_qw(int which){
    int bgrid; float* out;
    if (which==0){ bgrid=30; out=g_qw30; }
    else if (which==1){ bgrid=16; out=g_qw16; }
    else { bgrid=10; out=g_qw10; }
    int k = blockIdx.x*blockDim.x + threadIdx.x;
    if (k >= 2*bgrid) return;
    double beta = PI*(2*k+1)/(4.0*bgrid);
    double s = 0.0;
    for (int j=0;j<bgrid;j++)
        s += sin((double)(2*k+1)*(2*j+1)*PI/(4.0*bgrid))/(double)(2*j+1);
    out[k] = (float)((2.0/bgrid)*sin(beta)*s);
}

// ================= pipeline kernels =================
__global__ void k_zero_img(){
    int i = blockIdx.x*blockDim.x + threadIdx.x;
    if (i < BATCH*NA60*NA60) g_img[i] = 0.0f;
}

__global__ void k_project(const float* __restrict__ x){
    int tid = blockIdx.x*blockDim.x + threadIdx.x;
    if (tid >= BATCH*NPTS) return;
    int b = tid/NPTS, p = tid%NPTS;
    float xx = x[b*3*NPTS + 0*NPTS + p];
    float yy = x[b*3*NPTS + 1*NPTS + p];
    float zz = x[b*3*NPTS + 2*NPTS + p];
    float r  = sqrtf(xx*xx + yy*yy + zz*zz);
    float rc = fmaxf(r, 1e-8f);
    float cz = fminf(fmaxf(zz/rc, -1.0f), 1.0f);
    float beta  = acosf(cz);
    float alpha = atan2f(yy, xx);
    if (alpha < 0.0f) alpha += 2.0f*(float)PI;
    int bi = (int)(beta/(float)PI*60.0f);          bi = min(max(bi,0),59);
    int ai = (int)(alpha/(2.0f*(float)PI)*60.0f);  ai = min(max(ai,0),59);
    atomicMax((int*)&g_img[(b*NA60+bi)*NA60 + ai], __float_as_int(r));
}

// FFT over alpha at needed freqs m=-15..15
__global__ void k_ga(){
    int tid = blockIdx.x*blockDim.x + threadIdx.x;
    if (tid >= BATCH*NA60*MR1) return;
    int j = tid % MR1; int bk = tid / MR1;
    int m = j - 15;
    double sr=0.0, si=0.0;
    const float* row = g_img + bk*NA60;
    for (int a=0;a<NA60;a++){
        double s,c; sincospi(-2.0*m*a/60.0, &s, &c);
        double v = row[a];
        sr += v*c; si += v*s;
    }
    g_Ga[tid] = make_float2((float)sr,(float)si);
}

// s2_fft: X1[b][l,m] = (2pi/60) * sum_k qw30[k] d^l_{m,0}(b_k) Ga[b,k,m]
__global__ void k_x1(){
    int tid = blockIdx.x*blockDim.x + threadIdx.x;
    if (tid >= BATCH*NC1) return;
    int p = tid % NC1, b = tid / NC1;
    int l=0; while ((l+1)*(l+1) <= p) l++;
    int jm = p - l*l, m = jm - l;
    float ar=0.0f, ai=0.0f;
    for (int k=0;k<NA60;k++){
        float wd = g_qw30[k]*g_dcol30[k*NC1 + p];
        float2 ga = g_Ga[(b*NA60+k)*MR1 + (m+15)];
        ar += wd*ga.x; ai += wd*ga.y;
    }
    float sc = (float)(2.0*PI/60.0);
    g_X1[tid] = make_float2(ar*sc, ai*sc);
}

// DFT of s2 weights: Wh1[o,j] = sum_p w_s2[o,p] e^{-i 2pi p (j-15)/60}
__global__ void k_wh1(const float* __restrict__ w_s2){
    int tid = blockIdx.x*blockDim.x + threadIdx.x;
    if (tid >= F0*MR1) return;
    int j = tid % MR1, o = tid / MR1;
    int m = j - 15;
    double sr=0.0, si=0.0;
    const float* w = w_s2 + o*NA60;
    for (int p=0;p<NA60;p++){
        double s,c; sincospi(-2.0*p*m/60.0, &s, &c);
        sr += w[p]*c; si += w[p]*s;
    }
    g_Wh1[tid] = make_float2((float)sr,(float)si);
}

// Y1[o][l,m] = d^l_{m,0}(pi/2) * Wh1[o, m+15] / 60
__global__ void k_y1(){
    int tid = blockIdx.x*blockDim.x + threadIdx.x;
    if (tid >= F0*NC1) return;
    int p = tid % NC1, o = tid / NC1;
    int l=0; while ((l+1)*(l+1) <= p) l++;
    int m = (p - l*l) - l;
    float d = g_dhcol[p] * (1.0f/60.0f);
    float2 w = g_Wh1[o*MR1 + (m+15)];
    g_Y1[tid] = make_float2(d*w.x, d*w.y);
}

// layer-1 synthesis: one block per (b,o,k). Build M (31x31), then 2-stage iDFT -> 32x32 real
__global__ void k_syn1(){
    __shared__ float2 Msh[MR1*MR1];
    __shared__ float2 Tsh[MR1*N32];
    __shared__ float2 Xsh[NC1];
    __shared__ float2 Ysh[NC1];
    __shared__ float2 ctab[N32];
    int bid = blockIdx.x;            // ((b*F0+o)*32 + k)
    int k = bid % N32; int bo = bid / N32;
    int o = bo % F0;  int b = bo / F0;
    int t = threadIdx.x;
    for (int i=t;i<NC1;i+=256){ Xsh[i]=g_X1[b*NC1+i]; Ysh[i]=g_Y1[o*NC1+i]; }
    if (t < N32){ double s,c; sincospi(2.0*t/32.0,&s,&c); ctab[t]=make_float2((float)c,(float)s); }
    __syncthreads();
    const float* dk = g_d16 + k*NSQ1;
    for (int e=t; e<MR1*MR1; e+=256){
        int jm = e / MR1, jn = e % MR1;
        int m = jm-15, n = jn-15;
        int lmin = max(abs(m), abs(n));
        float ar=0.0f, ai=0.0f;
        for (int l=lmin; l<L1MAX; l++){
            float w = dk[offsq(l) + (m+l)*(2*l+1) + (n+l)] * (float)(2*l+1);
            float2 xv = Xsh[l*l + m+l];
            float2 yv = Ysh[l*l + n+l];
            ar += w*(xv.x*yv.x + xv.y*yv.y);    // X * conj(Y)
            ai += w*(xv.y*yv.x - xv.x*yv.y);
        }
        Msh[e] = make_float2(ar, ai);
    }
    __syncthreads();
    for (int e=t; e<MR1*N32; e+=256){
        int jm = e / N32, g = e % N32;
        float tr=0.0f, ti=0.0f;
        for (int jn=0;jn<MR1;jn++){
            int n = jn-15;
            int idx = ((g*n) % 32 + 32) % 32;
            float2 w = ctab[idx];
            float2 mm = Msh[jm*MR1+jn];
            tr += mm.x*w.x - mm.y*w.y;
            ti += mm.x*w.y + mm.y*w.x;
        }
        Tsh[e] = make_float2(tr,ti);
    }
    __syncthreads();
    float* hout = g_h1 + (size_t)bid * (N32*N32);
    for (int e=t; e<N32*N32; e+=256){
        int a = e / N32, g = e % N32;
        float acc=0.0f;
        for (int jm=0;jm<MR1;jm++){
            int m = jm-15;
            int idx = ((a*m) % 32 + 32) % 32;
            float2 w = ctab[idx];
            float2 tv = Tsh[jm*N32+g];
            acc += tv.x*w.x - tv.y*w.y;
        }
        hout[e] = acc;
    }
}

// batchnorm stats (bias skipped: cancels in BN)
__global__ void k_bn1stats(const float* __restrict__ gw, const float* __restrict__ gb){
    int c = blockIdx.x; int t = threadIdx.x;
    double s=0.0, s2=0.0;
    for (int idx=t; idx<BATCH*32768; idx+=256){
        int b = idx >> 15; int r = idx & 32767;
        float v = g_h1[((size_t)(b*F0+c)<<15) + r];
        s += v; s2 += (double)v*v;
    }
    __shared__ double sh[256], sh2[256];
    sh[t]=s; sh2[t]=s2; __syncthreads();
    for (int st=128; st>0; st>>=1){ if (t<st){ sh[t]+=sh[t+st]; sh2[t]+=sh2[t+st]; } __syncthreads(); }
    if (t==0){
        double N = (double)BATCH*32768.0;
        double mu = sh[0]/N;
        double var = sh2[0]/N - mu*mu;
        float a = gw[c] * (float)rsqrt(var + 1e-5);
        g_bn1a[c]=a; g_bn1bv[c]= gb[c] - (float)mu * a;
    }
}

__global__ void k_bn1apply(){
    size_t total = (size_t)BATCH*F0*32768;
    for (size_t i = (size_t)blockIdx.x*blockDim.x + threadIdx.x; i < total;
         i += (size_t)gridDim.x*blockDim.x){
        int c = (int)((i >> 15) % F0);
        float v = g_h1[i]*g_bn1a[c] + g_bn1bv[c];
        g_h1[i] = v>0.0f ? v : 0.0f;
    }
}

// fft2 over (alpha,gamma), truncated to m,n in -9..9
__global__ void k_g2(){
    __shared__ float  hsh[N32*N32];
    __shared__ float2 Ush[MR2*N32];
    __shared__ float2 ctab[N32];
    int bid = blockIdx.x;                    // (b*F0+c)*32 + k
    int t = threadIdx.x;
    const float* hin = g_h1 + (size_t)bid*1024;
    for (int i=t;i<1024;i+=256) hsh[i]=hin[i];
    if (t<N32){ double s,c; sincospi(2.0*t/32.0,&s,&c); ctab[t]=make_float2((float)c,(float)s); }
    __syncthreads();
    for (int e=t; e<MR2*N32; e+=256){
        int jm=e/N32, g=e%N32, m=jm-9;
        float ur=0.0f, ui=0.0f;
        for (int a=0;a<N32;a++){
            int idx = ((-(a*m)) % 32 + 32) % 32;
            float2 w = ctab[idx];
            float v = hsh[a*32+g];
            ur += v*w.x; ui += v*w.y;
        }
        Ush[e]=make_float2(ur,ui);
    }
    __syncthreads();
    float2* gout = g_G2 + (size_t)bid*(MR2*MR2);
    for (int e=t; e<MR2*MR2; e+=256){
        int jm=e/MR2, jn=e%MR2, n=jn-9;
        float gr=0.0f, gi=0.0f;
        for (int g=0; g<N32; g++){
            int idx = ((-(g*n)) % 32 + 32) % 32;
            float2 w = ctab[idx];
            float2 u = Ush[jm*N32+g];
            gr += u.x*w.x - u.y*w.y;
            gi += u.x*w.y + u.y*w.x;
        }
        gout[e]=make_float2(gr,gi);
    }
}

__device__ __forceinline__ void unpack_sq(int p, int &l, int &jm, int &jn){
    l=0; while (p >= (2*l+1)*(2*l+1)){ p -= (2*l+1)*(2*l+1); l++; }
    jm = p/(2*l+1); jn = p%(2*l+1);
}

// so3_fft beta contraction: X2 = (2pi/32)^2 sum_k qw16[k] d^l_k[m,n] G2[b,c,k,m,n]
__global__ void k_x2(){
    int tid = blockIdx.x*blockDim.x + threadIdx.x;
    if (tid >= BATCH*F0*NSQ2) return;
    int p = tid % NSQ2; int bc = tid / NSQ2;
    int l,jm,jn; unpack_sq(p,l,jm,jn);
    int gm = jm - l + 9, gn = jn - l + 9;
    float ar=0.0f, ai=0.0f;
    const float2* G = g_G2 + (size_t)bc*N32*(MR2*MR2);
    for (int k=0;k<N32;k++){
        float wd = g_qw16[k]*g_d16[k*NSQ1 + p];   // l<10 prefix of the l<16 table
        float2 gg = G[k*(MR2*MR2) + gm*MR2 + gn];
        ar += wd*gg.x; ai += wd*gg.y;
    }
    float sc = (float)((2.0*PI/32.0)*(2.0*PI/32.0));
    g_X2[tid] = make_float2(ar*sc, ai*sc);
}

// DFT of so3 weights: Wh2[i,o,j] = (1/32) sum_p w_so3[i,o,p] e^{-i 2pi p (j-9)/32}
__global__ void k_wh2(const float* __restrict__ w_so3){
    int tid = blockIdx.x*blockDim.x + threadIdx.x;
    if (tid >= F0*F1*MR2) return;
    int j = tid % MR2; int io = tid / MR2;
    int m = j - 9;
    double sr=0.0, si=0.0;
    const float* w = w_so3 + io*N32;
    for (int p=0;p<N32;p++){
        double s,c; sincospi(-2.0*p*m/32.0, &s, &c);
        sr += w[p]*c; si += w[p]*s;
    }
    g_Wh2[tid] = make_float2((float)(sr/32.0),(float)(si/32.0));
}

// A[b,i][l,m,n] = sum_k X2[b,i][l,m,k] d^l_{pi/2}[n,k]
__global__ void k_a(){
    int tid = blockIdx.x*blockDim.x + threadIdx.x;
    if (tid >= BATCH*F0*NSQ2) return;
    int p = tid % NSQ2; int bi = tid / NSQ2;
    int l,jm,jn; unpack_sq(p,l,jm,jn);
    int w = 2*l+1;
    const float2* X = g_X2 + (size_t)bi*NSQ2 + offsq(l) + jm*w;
    const float*  dd = g_dh10 + offsq(l) + jn*w;
    float ar=0.0f, ai=0.0f;
    for (int jk=0; jk<w; jk++){
        float d = dd[jk]; float2 xv = X[jk];
        ar += d*xv.x; ai += d*xv.y;
    }
    g_Aa[tid] = make_float2(ar,ai);
}

// Z2[b,o][l,m,n] = sum_i A[b,i][l,m,n] * conj(Wh2[i,o,n])
__global__ void k_z2(){
    int tid = blockIdx.x*blockDim.x + threadIdx.x;
    if (tid >= BATCH*F1*NSQ2) return;
    int p = tid % NSQ2; int bo = tid / NSQ2;
    int o = bo % F1; int b = bo / F1;
    int l,jm,jn; unpack_sq(p,l,jm,jn);
    int jw = jn - l + 9;
    float ar=0.0f, ai=0.0f;
    for (int i=0;i<F0;i++){
        float2 a = g_Aa[((size_t)(b*F0+i))*NSQ2 + p];
        float2 w = g_Wh2[(i*F1+o)*MR2 + jw];
        ar += a.x*w.x + a.y*w.y;
        ai += a.y*w.x - a.x*w.y;
    }
    g_Z2[tid] = make_float2(ar,ai);
}

// layer-2 synthesis: one block per (b,o,k); M (19x19) -> 20x20 real
__global__ void k_syn2(){
    __shared__ float2 Msh[MR2*MR2];
    __shared__ float2 Tsh[MR2*N20];
    __shared__ float2 ctab[N20];
    int bid = blockIdx.x;                     // ((b*F1+o)*20 + k)
    int k = bid % N20; int bo = bid / N20;
    int t = threadIdx.x;
    if (t < N20){ double s,c; sincospi(2.0*t/20.0,&s,&c); ctab[t]=make_float2((float)c,(float)s); }
    __syncthreads();
    const float2* Z = g_Z2 + (size_t)bo*NSQ2;
    const float*  dk = g_d10 + k*NSQ2;
    for (int e=t; e<MR2*MR2; e+=256){
        int jm=e/MR2, jn=e%MR2;
        int m=jm-9, n=jn-9;
        int lmin = max(abs(m), abs(n));
        float ar=0.0f, ai=0.0f;
        for (int l=lmin; l<L2MAX; l++){
            int idx = offsq(l) + (m+l)*(2*l+1) + (n+l);
            float w = dk[idx] * (float)(2*l+1);
            float2 z = Z[idx];
            ar += w*z.x; ai += w*z.y;
        }
        Msh[e] = make_float2(ar,ai);
    }
    __syncthreads();
    for (int e=t; e<MR2*N20; e+=256){
        int jm=e/N20, g=e%N20;
        float tr=0.0f, ti=0.0f;
        for (int jn=0;jn<MR2;jn++){
            int n=jn-9;
            int idx = ((g*n) % 20 + 20) % 20;
            float2 w = ctab[idx];
            float2 mm = Msh[jm*MR2+jn];
            tr += mm.x*w.x - mm.y*w.y;
            ti += mm.x*w.y + mm.y*w.x;
        }
        Tsh[e] = make_float2(tr,ti);
    }
    __syncthreads();
    float* hout = g_h2 + (size_t)bid*(N20*N20);
    for (int e=t; e<N20*N20; e+=256){
        int a=e/N20, g=e%N20;
        float acc=0.0f;
        for (int jm=0;jm<MR2;jm++){
            int m=jm-9;
            int idx = ((a*m) % 20 + 20) % 20;
            float2 w = ctab[idx];
            float2 tv = Tsh[jm*N20+g];
            acc += tv.x*w.x - tv.y*w.y;
        }
        hout[e] = acc;
    }
}

__global__ void k_bn2stats(const float* __restrict__ gw, const float* __restrict__ gb){
    int c = blockIdx.x; int t = threadIdx.x;
    double s=0.0, s2=0.0;
    const int per = N20*N20*N20;   // 8000
    for (int idx=t; idx<BATCH*per; idx+=256){
        int b = idx/per; int r = idx%per;
        float v = g_h2[(size_t)(b*F1+c)*per + r];
        s += v; s2 += (double)v*v;
    }
    __shared__ double sh[256], sh2[256];
    sh[t]=s; sh2[t]=s2; __syncthreads();
    for (int st=128; st>0; st>>=1){ if (t<st){ sh[t]+=sh[t+st]; sh2[t]+=sh2[t+st]; } __syncthreads(); }
    if (t==0){
        double N = (double)BATCH*per;
        double mu = sh[0]/N;
        double var = sh2[0]/N - mu*mu;
        float a = gw[c] * (float)rsqrt(var + 1e-5);
        g_bn2a[c]=a; g_bn2bv[c]= gb[c] - (float)mu * a;
    }
}

// fused BN2-apply + relu + so3_integrate
__global__ void k_integrate(){
    int bf = blockIdx.x;                  // b*F1+f
    int f = bf % F1;
    int t = threadIdx.x;
    float a = g_bn2a[f], bb = g_bn2bv[f];
    double s = 0.0;
    const float* h = g_h2 + (size_t)bf*(N20*N20*N20);
    for (int idx=t; idx<N20*N20*N20; idx+=256){
        int k = idx/(N20*N20);
        float v = h[idx]*a + bb;
        v = v>0.0f ? v : 0.0f;
        s += (double)v * (double)g_qw10[k];
    }
    __shared__ double sh[256];
    sh[t]=s; __syncthreads();
    for (int st=128; st>0; st>>=1){ if (t<st) sh[t]+=sh[t+st]; __syncthreads(); }
    if (t==0){
        double sc = (2.0*PI/20.0)*(2.0*PI/20.0);
        g_feat[bf] = (float)(sh[0]*sc);
    }
}

__global__ void k_lin(const float* __restrict__ lw, const float* __restrict__ lb,
                      float* __restrict__ out){
    int tid = blockIdx.x*blockDim.x + threadIdx.x;
    if (tid >= BATCH*NCLS) return;
    int c = tid % NCLS, b = tid / NCLS;
    float acc = lb[c];
    for (int f=0; f<F1; f++) acc += g_feat[b*F1+f]*lw[f*NCLS+c];
    out[tid] = acc;
}

// ================= host orchestration =================
extern "C" void kernel_launch(void* const* d_in, const int* in_sizes, int n_in,
                              void* d_out, int out_size){
    const float* x     = (const float*)d_in[0];
    const float* w_s2  = (const float*)d_in[1];
    const float* bn1g  = (const float*)d_in[3];
    const float* bn1b  = (const float*)d_in[4];
    const float* w_so3 = (const float*)d_in[5];
    const float* bn2g  = (const float*)d_in[7];
    const float* bn2b  = (const float*)d_in[8];
    const float* linw  = (const float*)d_in[9];
    const float* linb  = (const float*)d_in[10];
    float* out = (float*)d_out;

    // --- setup tables ---
    k_qw<<<1,64>>>(0);
    k_qw<<<1,64>>>(1);
    k_qw<<<1,64>>>(2);
    k_wig_full<<<(N32*NSQ1+255)/256,256>>>(0);
    k_wig_full<<<(N20*NSQ2+255)/256,256>>>(1);
    k_wig_full<<<(NSQ2+255)/256,256>>>(2);
    k_wig_col<<<(NA60*NC1+255)/256,256>>>(0);
    k_wig_col<<<1,256>>>(1);

    // --- pipeline ---
    k_zero_img<<<(BATCH*NA60*NA60+255)/256,256>>>();
    k_project<<<(BATCH*NPTS+255)/256,256>>>(x);
    k_ga<<<(BATCH*NA60*MR1+255)/256,256>>>();
    k_x1<<<(BATCH*NC1+255)/256,256>>>();
    k_wh1<<<(F0*MR1+255)/256,256>>>(w_s2);
    k_y1<<<(F0*NC1+255)/256,256>>>();
    k_syn1<<<BATCH*F0*N32,256>>>();
    k_bn1stats<<<F0,256>>>(bn1g, bn1b);
    k_bn1apply<<<8192,256>>>();
    k_g2<<<BATCH*F0*N32,256>>>();
    k_x2<<<(BATCH*F0*NSQ2+255)/256,256>>>();
    k_wh2<<<(F0*F1*MR2+255)/256,256>>>(w_so3);
    k_a<<<(BATCH*F0*NSQ2+255)/256,256>>>();
    k_z2<<<(BATCH*F1*NSQ2+255)/256,256>>>();
    k_syn2<<<BATCH*F1*N20,256>>>();
    k_bn2stats<<<F1,256>>>(bn2g, bn2b);
    k_integrate<<<BATCH*F1,256>>>();
    k_lin<<<(BATCH*NCLS+255)/256,256>>>(linw, linb, out);
}

// round 5
// speedup vs baseline: 1.6174x; 1.6174x over previous
#include <cuda_runtime.h>
#include <math.h>

#define PI 3.14159265358979323846

#define BATCH 8
#define NPTS  1024
#define F0    100
#define F1    100
#define NCLS  40

#define NA60  60
#define L1MAX 16
#define N32   32
#define L2MAX 10
#define N20   20

#define NC1   256
#define NSQ1  5456
#define NSQ2  1330
#define MR1   31
#define MR2   19

__device__ __forceinline__ int offsq(int l){ return l*(4*l*l-1)/3; }

// ---------------- scratch ----------------
__device__ float  g_img[BATCH*NA60*NA60];
__device__ float2 g_Ga [BATCH*NA60*MR1];
__device__ float2 g_X1 [BATCH*NC1];
__device__ float2 g_Wh1[F0*MR1];
__device__ float2 g_Y1 [F0*NC1];
__device__ float  g_h1 [BATCH*F0*N32*N32*N32];
__device__ float  g_bn1a[F0], g_bn1bv[F0];
__device__ float2 g_G2 [BATCH*F0*N32*MR2*MR2];
__device__ float2 g_X2 [BATCH*F0*NSQ2];
__device__ float2 g_Wh2[F0*F1*MR2];
__device__ float2 g_Aa [BATCH*F0*NSQ2];
__device__ float2 g_Z2 [BATCH*F1*NSQ2];
__device__ float  g_h2 [BATCH*F1*N20*N20*N20];
__device__ float  g_bn2a[F1], g_bn2bv[F1];
__device__ float  g_feat[BATCH*F1];
__device__ double2 g_s1p[BATCH*F0*N32];   // per-block (sum,sumsq) from k_syn1
__device__ double2 g_s2p[BATCH*F1*N20];   // per-block partials from k_syn2

// ---------------- tables ----------------
__device__ float g_d16   [N32*NSQ1];   // raw d^l at dh(16) betas (used by k_x2, l<10 prefix)
__device__ float g_d16w  [N32*NSQ1];   // (2l+1)*d  (used by k_syn1)
__device__ float g_d10w  [N20*NSQ2];   // (2l+1)*d at dh(10) betas (k_syn2)
__device__ float g_dcol30[NA60*NC1];
__device__ float g_dhcol [NC1];
__device__ float g_dh10  [NSQ2];       // raw d at pi/2 (k_a)
__device__ float g_qw30[NA60], g_qw16[N32], g_qw10[N20];

// ============ Wigner-d: factorial init + term-ratio recurrence (double) ============
__device__ double d_ipow(double x, int n){ double r=1.0; for(int i=0;i<n;i++) r*=x; return r; }

__device__ double d_wig(int l, int mp, int m, double beta){
    if (l == 0) return 1.0;
    double f[32]; f[0]=1.0;
    for (int i=1;i<32;i++) f[i]=f[i-1]*(double)i;
    double cb = cos(0.5*beta), sb = sin(0.5*beta);
    int smin = max(0, m-mp);
    int smax = min(l+m, l-mp);
    double pref = sqrt(f[l+mp]*f[l-mp]*f[l+m]*f[l-m]);
    // initial term at s=smin
    double term = d_ipow(cb, 2*l+m-mp-2*smin) * d_ipow(sb, mp-m+2*smin)
                / (f[l+m-smin]*f[smin]*f[mp-m+smin]*f[l-mp-smin]);
    if ((mp-m+smin)&1) term = -term;
    double acc = term;
    double r2 = (sb*sb)/(cb*cb);
    for (int s=smin; s<smax; s++){
        term *= -r2 * (double)((l+m-s)*(l-mp-s)) / ((double)(s+1)*(double)(mp-m+s+1));
        acc += term;
    }
    return pref*acc;
}

// ============ single merged setup kernel ============
#define T0 (N32*NSQ1)     // d16 + d16w
#define T1 (N20*NSQ2)     // d10w
#define T2 (NSQ2)         // dh10
#define T3 (NA60*NC1)     // dcol30
#define T4 (NC1)          // dhcol
#define T5 (112)          // qw
#define TSETUP (T0+T1+T2+T3+T4+T5)

__global__ void k_setup(){
    int tid = blockIdx.x*blockDim.x + threadIdx.x;
    if (tid >= TSETUP) return;
    if (tid < T0){
        int k = tid/NSQ1, p = tid%NSQ1;
        int l=0; while (p >= (2*l+1)*(2*l+1)){ p -= (2*l+1)*(2*l+1); l++; }
        int jm = p/(2*l+1), jn = p%(2*l+1);
        double beta = PI*(2*k+1)/64.0;
        float v = (float)d_wig(l, jm-l, jn-l, beta);
        g_d16 [tid] = v;
        g_d16w[tid] = v*(float)(2*l+1);
        return;
    }
    tid -= T0;
    if (tid < T1){
        int k = tid/NSQ2, p = tid%NSQ2;
        int l=0; while (p >= (2*l+1)*(2*l+1)){ p -= (2*l+1)*(2*l+1); l++; }
        int jm = p/(2*l+1), jn = p%(2*l+1);
        double beta = PI*(2*k+1)/40.0;
        g_d10w[tid] = (float)(d_wig(l, jm-l, jn-l, beta)*(double)(2*l+1));
        return;
    }
    tid -= T1;
    if (tid < T2){
        int p = tid;
        int l=0; while (p >= (2*l+1)*(2*l+1)){ p -= (2*l+1)*(2*l+1); l++; }
        int jm = p/(2*l+1), jn = p%(2*l+1);
        g_dh10[tid] = (float)d_wig(l, jm-l, jn-l, 0.5*PI);
        return;
    }
    tid -= T2;
    if (tid < T3){
        int k = tid/NC1, p = tid%NC1;
        int l=0; while ((l+1)*(l+1) <= p) l++;
        int jm = p - l*l;
        double beta = PI*(2*k+1)/120.0;
        g_dcol30[tid] = (float)d_wig(l, jm-l, 0, beta);
        return;
    }
    tid -= T3;
    if (tid < T4){
        int p = tid;
        int l=0; while ((l+1)*(l+1) <= p) l++;
        int jm = p - l*l;
        g_dhcol[tid] = (float)d_wig(l, jm-l, 0, 0.5*PI);
        return;
    }
    tid -= T4;
    { // quadrature weights
        int bgrid, k; float* out;
        if (tid < 60){ bgrid=30; out=g_qw30; k=tid; }
        else if (tid < 92){ bgrid=16; out=g_qw16; k=tid-60; }
        else { bgrid=10; out=g_qw10; k=tid-92; }
        double beta = PI*(2*k+1)/(4.0*bgrid);
        double s = 0.0;
        for (int j=0;j<bgrid;j++)
            s += sin((double)(2*k+1)*(2*j+1)*PI/(4.0*bgrid))/(double)(2*j+1);
        out[k] = (float)((2.0/bgrid)*sin(beta)*s);
    }
}

// ============ pipeline ============
__global__ void k_zero_img(){
    int i = blockIdx.x*blockDim.x + threadIdx.x;
    if (i < BATCH*NA60*NA60) g_img[i] = 0.0f;
}

__global__ void k_project(const float* __restrict__ x){
    int tid = blockIdx.x*blockDim.x + threadIdx.x;
    if (tid >= BATCH*NPTS) return;
    int b = tid/NPTS, p = tid%NPTS;
    float xx = x[b*3*NPTS + 0*NPTS + p];
    float yy = x[b*3*NPTS + 1*NPTS + p];
    float zz = x[b*3*NPTS + 2*NPTS + p];
    float r  = sqrtf(xx*xx + yy*yy + zz*zz);
    float rc = fmaxf(r, 1e-8f);
    float cz = fminf(fmaxf(zz/rc, -1.0f), 1.0f);
    float beta  = acosf(cz);
    float alpha = atan2f(yy, xx);
    if (alpha < 0.0f) alpha += 2.0f*(float)PI;
    int bi = (int)(beta/(float)PI*60.0f);          bi = min(max(bi,0),59);
    int ai = (int)(alpha/(2.0f*(float)PI)*60.0f);  ai = min(max(ai,0),59);
    atomicMax((int*)&g_img[(b*NA60+bi)*NA60 + ai], __float_as_int(r));
}

// alpha-DFT at m=-15..15 via 60-entry table
__global__ void k_ga(){
    __shared__ float2 tab[NA60];   // e^{-2pi i t/60}
    int t = threadIdx.x;
    if (t < NA60){ double s,c; sincospi(-2.0*t/60.0,&s,&c); tab[t]=make_float2((float)c,(float)s); }
    __syncthreads();
    int tid = blockIdx.x*blockDim.x + t;
    if (tid >= BATCH*NA60*MR1) return;
    int j = tid % MR1; int bk = tid / MR1;
    int m = j - 15;
    int inc = ((m%60)+60)%60;
    float sr=0.0f, si=0.0f;
    const float* row = g_img + bk*NA60;
    int idx=0;
    #pragma unroll 4
    for (int a=0;a<NA60;a++){
        float2 w = tab[idx];
        float v = row[a];
        sr += v*w.x; si += v*w.y;
        idx += inc; if (idx>=60) idx-=60;
    }
    g_Ga[tid] = make_float2(sr,si);
}

__global__ void k_x1(){
    int tid = blockIdx.x*blockDim.x + threadIdx.x;
    if (tid >= BATCH*NC1) return;
    int p = tid % NC1, b = tid / NC1;
    int l=0; while ((l+1)*(l+1) <= p) l++;
    int m = (p - l*l) - l;
    float ar=0.0f, ai=0.0f;
    for (int k=0;k<NA60;k++){
        float wd = g_qw30[k]*g_dcol30[k*NC1 + p];
        float2 ga = g_Ga[(b*NA60+k)*MR1 + (m+15)];
        ar += wd*ga.x; ai += wd*ga.y;
    }
    float sc = (float)(2.0*PI/60.0);
    g_X1[tid] = make_float2(ar*sc, ai*sc);
}

__global__ void k_wh1(const float* __restrict__ w_s2){
    __shared__ float2 tab[NA60];
    int t = threadIdx.x;
    if (t < NA60){ double s,c; sincospi(-2.0*t/60.0,&s,&c); tab[t]=make_float2((float)c,(float)s); }
    __syncthreads();
    int tid = blockIdx.x*blockDim.x + t;
    if (tid >= F0*MR1) return;
    int j = tid % MR1, o = tid / MR1;
    int m = j - 15;
    int inc = ((m%60)+60)%60;
    float sr=0.0f, si=0.0f;
    const float* w = w_s2 + o*NA60;
    int idx=0;
    for (int p=0;p<NA60;p++){
        float2 e = tab[idx];
        sr += w[p]*e.x; si += w[p]*e.y;
        idx += inc; if (idx>=60) idx-=60;
    }
    g_Wh1[tid] = make_float2(sr,si);
}

__global__ void k_y1(){
    int tid = blockIdx.x*blockDim.x + threadIdx.x;
    if (tid >= F0*NC1) return;
    int p = tid % NC1, o = tid / NC1;
    int l=0; while ((l+1)*(l+1) <= p) l++;
    int m = (p - l*l) - l;
    float d = g_dhcol[p] * (1.0f/60.0f);
    float2 w = g_Wh1[o*MR1 + (m+15)];
    g_Y1[tid] = make_float2(d*w.x, d*w.y);
}

// layer-1 synthesis + bn1 partial stats. One block per (b,o,k).
__global__ void k_syn1(){
    __shared__ float2 Xsh[NC1], Ysh[NC1];
    __shared__ float2 Msh[MR1*MR1];
    __shared__ float2 Tsh[MR1*N32];
    __shared__ float2 ctab[N32];
    __shared__ double red[256], red2[256];
    int bid = blockIdx.x;
    int k = bid & 31; int bo = bid >> 5;
    int o = bo % F0;  int b = bo / F0;
    int t = threadIdx.x;
    for (int i=t;i<NC1;i+=256){ Xsh[i]=g_X1[b*NC1+i]; Ysh[i]=g_Y1[o*NC1+i]; }
    if (t < N32){ double s,c; sincospi(2.0*t/32.0,&s,&c); ctab[t]=make_float2((float)c,(float)s); }
    __syncthreads();
    const float* dk = g_d16w + k*NSQ1;
    for (int e=t; e<MR1*MR1; e+=256){
        int jm = e / MR1, jn = e % MR1;
        int m = jm-15, n = jn-15;
        int lmin = max(abs(m), abs(n));
        float ar=0.0f, ai=0.0f;
        for (int l=lmin; l<L1MAX; l++){
            float w = dk[offsq(l) + (m+l)*(2*l+1) + (n+l)];
            float2 xv = Xsh[l*l + m+l];
            float2 yv = Ysh[l*l + n+l];
            ar += w*(xv.x*yv.x + xv.y*yv.y);
            ai += w*(xv.y*yv.x - xv.x*yv.y);
        }
        Msh[e] = make_float2(ar, ai);
    }
    __syncthreads();
    // stage T: warp-uniform jm, Msh broadcast
    {
        int g = t & 31, warp = t >> 5;
        for (int jm=warp; jm<MR1; jm+=8){
            float tr=0.0f, ti=0.0f;
            int idx = (g*17) & 31;             // n=-15 start
            #pragma unroll
            for (int jn=0;jn<MR1;jn++){
                float2 w = ctab[idx];
                float2 mm = Msh[jm*MR1+jn];    // broadcast
                tr += mm.x*w.x - mm.y*w.y;
                ti += mm.x*w.y + mm.y*w.x;
                idx = (idx+g) & 31;
            }
            Tsh[jm*N32+g] = make_float2(tr,ti);
        }
    }
    __syncthreads();
    // stage H: warp-uniform a, ctab broadcast; accumulate bn stats
    float* hout = g_h1 + (size_t)bid * 1024;
    double ls=0.0, ls2=0.0;
    {
        int g = t & 31, warp = t >> 5;
        for (int a=warp; a<N32; a+=8){
            float acc=0.0f;
            int idx = (a*17) & 31;             // m=-15 start
            #pragma unroll
            for (int jm=0;jm<MR1;jm++){
                float2 w = ctab[idx];          // broadcast
                float2 tv = Tsh[jm*N32+g];
                acc += tv.x*w.x - tv.y*w.y;
                idx = (idx+a) & 31;
            }
            hout[a*32+g] = acc;
            ls += acc; ls2 += (double)acc*acc;
        }
    }
    red[t]=ls; red2[t]=ls2; __syncthreads();
    for (int st=128; st>0; st>>=1){ if (t<st){ red[t]+=red[t+st]; red2[t]+=red2[t+st]; } __syncthreads(); }
    if (t==0) g_s1p[bid] = make_double2(red[0], red2[0]);
}

// reduce bn1 partials per channel
__global__ void k_bn1fin(const float* __restrict__ gw, const float* __restrict__ gb){
    int o = blockIdx.x; int t = threadIdx.x;   // 256 threads = (b,k)
    int b = t >> 5, k = t & 31;
    double2 p = g_s1p[b*3200 + o*32 + k];
    __shared__ double sh[256], sh2[256];
    sh[t]=p.x; sh2[t]=p.y; __syncthreads();
    for (int st=128; st>0; st>>=1){ if (t<st){ sh[t]+=sh[t+st]; sh2[t]+=sh2[t+st]; } __syncthreads(); }
    if (t==0){
        double N = (double)BATCH*32768.0;
        double mu = sh[0]/N;
        double var = sh2[0]/N - mu*mu;
        float a = gw[o] * (float)rsqrt(var + 1e-5);
        g_bn1a[o]=a; g_bn1bv[o]= gb[o] - (float)mu * a;
    }
}

// fused BN+relu + truncated fft2 over (alpha,gamma)
__global__ void k_g2(){
    __shared__ float  hsh[N32*N32];
    __shared__ float2 Ush[MR2*N32];
    __shared__ float2 ctab[N32];
    int bid = blockIdx.x;
    int t = threadIdx.x;
    int c = (bid >> 5) % F0;
    float a1 = g_bn1a[c], b1 = g_bn1bv[c];
    const float* hin = g_h1 + (size_t)bid*1024;
    for (int i=t;i<1024;i+=256){ float v = hin[i]*a1 + b1; hsh[i] = v>0.0f ? v : 0.0f; }
    if (t<N32){ double s,cc; sincospi(2.0*t/32.0,&s,&cc); ctab[t]=make_float2((float)cc,(float)s); }
    __syncthreads();
    // stage U: warp-uniform jm
    {
        int g = t & 31, warp = t >> 5;
        for (int jm=warp; jm<MR2; jm+=8){
            int m = jm-9;
            float ur=0.0f, ui=0.0f;
            int idx=0, inc=(-m)&31;
            #pragma unroll
            for (int a=0;a<N32;a++){
                float2 w = ctab[idx];          // broadcast
                float v = hsh[a*32+g];
                ur += v*w.x; ui += v*w.y;
                idx = (idx+inc)&31;
            }
            Ush[jm*N32+g]=make_float2(ur,ui);
        }
    }
    __syncthreads();
    float2* gout = g_G2 + (size_t)bid*(MR2*MR2);
    for (int e=t; e<MR2*MR2; e+=256){
        int jm=e/MR2, jn=e%MR2, n=jn-9;
        float gr=0.0f, gi=0.0f;
        int idx=0, inc=(-n)&31;
        #pragma unroll
        for (int g=0; g<N32; g++){
            float2 w = ctab[idx];
            float2 u = Ush[jm*N32+g];
            gr += u.x*w.x - u.y*w.y;
            gi += u.x*w.y + u.y*w.x;
            idx=(idx+inc)&31;
        }
        gout[e]=make_float2(gr,gi);
    }
}

__device__ __forceinline__ void unpack_sq(int p, int &l, int &jm, int &jn){
    l=0; while (p >= (2*l+1)*(2*l+1)){ p -= (2*l+1)*(2*l+1); l++; }
    jm = p/(2*l+1); jn = p%(2*l+1);
}

__global__ void k_x2(){
    int tid = blockIdx.x*blockDim.x + threadIdx.x;
    if (tid >= BATCH*F0*NSQ2) return;
    int p = tid % NSQ2; int bc = tid / NSQ2;
    int l,jm,jn; unpack_sq(p,l,jm,jn);
    int gm = jm - l + 9, gn = jn - l + 9;
    float ar=0.0f, ai=0.0f;
    const float2* G = g_G2 + (size_t)bc*N32*(MR2*MR2);
    #pragma unroll 4
    for (int k=0;k<N32;k++){
        float wd = g_qw16[k]*g_d16[k*NSQ1 + p];
        float2 gg = G[k*(MR2*MR2) + gm*MR2 + gn];
        ar += wd*gg.x; ai += wd*gg.y;
    }
    float sc = (float)((2.0*PI/32.0)*(2.0*PI/32.0));
    g_X2[tid] = make_float2(ar*sc, ai*sc);
}

__global__ void k_wh2(const float* __restrict__ w_so3){
    __shared__ float2 tab[N32];    // e^{-2pi i t/32}
    int t = threadIdx.x;
    if (t<N32){ double s,c; sincospi(-2.0*t/32.0,&s,&c); tab[t]=make_float2((float)c,(float)s); }
    __syncthreads();
    int tid = blockIdx.x*blockDim.x + t;
    if (tid >= F0*F1*MR2) return;
    int j = tid % MR2; int io = tid / MR2;
    int m = j - 9;
    int inc = m & 31;
    float sr=0.0f, si=0.0f;
    const float* w = w_so3 + io*N32;
    int idx=0;
    #pragma unroll
    for (int p=0;p<N32;p++){
        float2 e = tab[idx];
        sr += w[p]*e.x; si += w[p]*e.y;
        idx=(idx+inc)&31;
    }
    g_Wh2[tid] = make_float2(sr*(1.0f/32.0f), si*(1.0f/32.0f));
}

__global__ void k_a(){
    int tid = blockIdx.x*blockDim.x + threadIdx.x;
    if (tid >= BATCH*F0*NSQ2) return;
    int p = tid % NSQ2; int bi = tid / NSQ2;
    int l,jm,jn; unpack_sq(p,l,jm,jn);
    int w = 2*l+1;
    const float2* X = g_X2 + (size_t)bi*NSQ2 + offsq(l) + jm*w;
    const float*  dd = g_dh10 + offsq(l) + jn*w;
    float ar=0.0f, ai=0.0f;
    for (int jk=0; jk<w; jk++){
        float d = dd[jk]; float2 xv = X[jk];
        ar += d*xv.x; ai += d*xv.y;
    }
    g_Aa[tid] = make_float2(ar,ai);
}

// Z2 with 4-way o tiling: thread = (b, oq, p), o = oq + {0,25,50,75}
__global__ void k_z2(){
    int tid = blockIdx.x*blockDim.x + threadIdx.x;
    if (tid >= BATCH*25*NSQ2) return;
    int p = tid % NSQ2; int rest = tid / NSQ2;
    int oq = rest % 25; int b = rest / 25;
    int l,jm,jn; unpack_sq(p,l,jm,jn);
    int jw = jn - l + 9;
    float ar0=0,ai0=0,ar1=0,ai1=0,ar2=0,ai2=0,ar3=0,ai3=0;
    const float2* A = g_Aa + (size_t)b*F0*NSQ2 + p;
    const float2* W = g_Wh2 + oq*MR2 + jw;
    #pragma unroll 2
    for (int i=0;i<F0;i++){
        float2 a = A[(size_t)i*NSQ2];
        const float2* Wi = W + (size_t)i*F1*MR2;
        float2 w0 = Wi[0*25*MR2];
        float2 w1 = Wi[1*25*MR2];
        float2 w2 = Wi[2*25*MR2];
        float2 w3 = Wi[3*25*MR2];
        ar0 += a.x*w0.x + a.y*w0.y;  ai0 += a.y*w0.x - a.x*w0.y;
        ar1 += a.x*w1.x + a.y*w1.y;  ai1 += a.y*w1.x - a.x*w1.y;
        ar2 += a.x*w2.x + a.y*w2.y;  ai2 += a.y*w2.x - a.x*w2.y;
        ar3 += a.x*w3.x + a.y*w3.y;  ai3 += a.y*w3.x - a.x*w3.y;
    }
    size_t base = (size_t)(b*F1)*NSQ2 + p;
    g_Z2[base + (size_t)(oq   )*NSQ2] = make_float2(ar0,ai0);
    g_Z2[base + (size_t)(oq+25)*NSQ2] = make_float2(ar1,ai1);
    g_Z2[base + (size_t)(oq+50)*NSQ2] = make_float2(ar2,ai2);
    g_Z2[base + (size_t)(oq+75)*NSQ2] = make_float2(ar3,ai3);
}

// layer-2 synthesis + bn2 partials. One block per (b,o,k).
__global__ void k_syn2(){
    __shared__ float2 Msh[MR2*MR2];
    __shared__ float2 Tsh[MR2*N20];
    __shared__ float2 ctab[N20];
    __shared__ double red[256], red2[256];
    int bid = blockIdx.x;
    int k = bid % N20; int bo = bid / N20;
    int t = threadIdx.x;
    if (t < N20){ double s,c; sincospi(2.0*t/20.0,&s,&c); ctab[t]=make_float2((float)c,(float)s); }
    __syncthreads();
    const float2* Z = g_Z2 + (size_t)bo*NSQ2;
    const float*  dk = g_d10w + k*NSQ2;
    for (int e=t; e<MR2*MR2; e+=256){
        int jm=e/MR2, jn=e%MR2;
        int m=jm-9, n=jn-9;
        int lmin = max(abs(m), abs(n));
        float ar=0.0f, ai=0.0f;
        for (int l=lmin; l<L2MAX; l++){
            int idx = offsq(l) + (m+l)*(2*l+1) + (n+l);
            float w = dk[idx];
            float2 z = Z[idx];
            ar += w*z.x; ai += w*z.y;
        }
        Msh[e] = make_float2(ar,ai);
    }
    __syncthreads();
    for (int e=t; e<MR2*N20; e+=256){
        int jm=e/N20, g=e%N20;
        float tr=0.0f, ti=0.0f;
        int idx=(g*11)%20, inc=g;            // n=-9 start: (-9g)%20 == (11g)%20
        #pragma unroll
        for (int jn=0;jn<MR2;jn++){
            float2 w = ctab[idx];
            float2 mm = Msh[jm*MR2+jn];
            tr += mm.x*w.x - mm.y*w.y;
            ti += mm.x*w.y + mm.y*w.x;
            idx += inc; if (idx>=20) idx-=20;
        }
        Tsh[e] = make_float2(tr,ti);
    }
    __syncthreads();
    float* hout = g_h2 + (size_t)bid*(N20*N20);
    double ls=0.0, ls2=0.0;
    for (int e=t; e<N20*N20; e+=256){
        int a=e/N20, g=e%N20;
        float acc=0.0f;
        int idx=(a*11)%20, inc=a;
        #pragma unroll
        for (int jm=0;jm<MR2;jm++){
            float2 w = ctab[idx];
            float2 tv = Tsh[jm*N20+g];
            acc += tv.x*w.x - tv.y*w.y;
            idx += inc; if (idx>=20) idx-=20;
        }
        hout[e] = acc;
        ls += acc; ls2 += (double)acc*acc;
    }
    red[t]=ls; red2[t]=ls2; __syncthreads();
    for (int st=128; st>0; st>>=1){ if (t<st){ red[t]+=red[t+st]; red2[t]+=red2[t+st]; } __syncthreads(); }
    if (t==0) g_s2p[bid] = make_double2(red[0], red2[0]);
}

__global__ void k_bn2fin(const float* __restrict__ gw, const float* __restrict__ gb){
    int o = blockIdx.x; int t = threadIdx.x;   // 160 active = (b,k)
    double s=0.0, s2=0.0;
    if (t < 160){
        int b = t/20, k = t%20;
        double2 p = g_s2p[b*2000 + o*20 + k];
        s=p.x; s2=p.y;
    }
    __shared__ double sh[256], sh2[256];
    sh[t]=s; sh2[t]=s2; __syncthreads();
    for (int st=128; st>0; st>>=1){ if (t<st){ sh[t]+=sh[t+st]; sh2[t]+=sh2[t+st]; } __syncthreads(); }
    if (t==0){
        double N = (double)BATCH*8000.0;
        double mu = sh[0]/N;
        double var = sh2[0]/N - mu*mu;
        float a = gw[o] * (float)rsqrt(var + 1e-5);
        g_bn2a[o]=a; g_bn2bv[o]= gb[o] - (float)mu * a;
    }
}

__global__ void k_integrate(){
    int bf = blockIdx.x;
    int f = bf % F1;
    int t = threadIdx.x;
    float a = g_bn2a[f], bb = g_bn2bv[f];
    double s = 0.0;
    const float* h = g_h2 + (size_t)bf*(N20*N20*N20);
    for (int idx=t; idx<N20*N20*N20; idx+=256){
        int k = idx/(N20*N20);
        float v = h[idx]*a + bb;
        v = v>0.0f ? v : 0.0f;
        s += (double)v * (double)g_qw10[k];
    }
    __shared__ double sh[256];
    sh[t]=s; __syncthreads();
    for (int st=128; st>0; st>>=1){ if (t<st) sh[t]+=sh[t+st]; __syncthreads(); }
    if (t==0){
        double sc = (2.0*PI/20.0)*(2.0*PI/20.0);
        g_feat[bf] = (float)(sh[0]*sc);
    }
}

__global__ void k_lin(const float* __restrict__ lw, const float* __restrict__ lb,
                      float* __restrict__ out){
    int tid = blockIdx.x*blockDim.x + threadIdx.x;
    if (tid >= BATCH*NCLS) return;
    int c = tid % NCLS, b = tid / NCLS;
    float acc = lb[c];
    for (int f=0; f<F1; f++) acc += g_feat[b*F1+f]*lw[f*NCLS+c];
    out[tid] = acc;
}

// ================= host =================
extern "C" void kernel_launch(void* const* d_in, const int* in_sizes, int n_in,
                              void* d_out, int out_size){
    const float* x     = (const float*)d_in[0];
    const float* w_s2  = (const float*)d_in[1];
    const float* bn1g  = (const float*)d_in[3];
    const float* bn1b  = (const float*)d_in[4];
    const float* w_so3 = (const float*)d_in[5];
    const float* bn2g  = (const float*)d_in[7];
    const float* bn2b  = (const float*)d_in[8];
    const float* linw  = (const float*)d_in[9];
    const float* linb  = (const float*)d_in[10];
    float* out = (float*)d_out;

    k_setup<<<(TSETUP+255)/256,256>>>();
    k_zero_img<<<(BATCH*NA60*NA60+255)/256,256>>>();
    k_project<<<(BATCH*NPTS+255)/256,256>>>(x);
    k_ga<<<(BATCH*NA60*MR1+255)/256,256>>>();
    k_x1<<<(BATCH*NC1+255)/256,256>>>();
    k_wh1<<<(F0*MR1+255)/256,256>>>(w_s2);
    k_y1<<<(F0*NC1+255)/256,256>>>();
    k_syn1<<<BATCH*F0*N32,256>>>();
    k_bn1fin<<<F0,256>>>(bn1g, bn1b);
    k_g2<<<BATCH*F0*N32,256>>>();
    k_x2<<<(BATCH*F0*NSQ2+255)/256,256>>>();
    k_wh2<<<(F0*F1*MR2+255)/256,256>>>(w_so3);
    k_a<<<(BATCH*F0*NSQ2+255)/256,256>>>();
    k_z2<<<(BATCH*25*NSQ2+255)/256,256>>>();
    k_syn2<<<BATCH*F1*N20,256>>>();
    k_bn2fin<<<F1,256>>>(bn2g, bn2b);
    k_integrate<<<BATCH*F1,256>>>();
    k_lin<<<(BATCH*NCLS+255)/256,256>>>(linw, linb, out);
}

// round 7
// speedup vs baseline: 2.7366x; 1.6920x over previous
#include <cuda_runtime.h>
#include <math.h>

#define PI 3.14159265358979323846

#define BATCH 8
#define NPTS  1024
#define F0    100
#define F1    100
#define NCLS  40

#define NA60  60
#define L1MAX 16
#define N32   32
#define L2MAX 10
#define N20   20

#define NC1   256
#define NH1   2856   // sum_{l<16} (l+1)(2l+1)  (m>=0 half)
#define NH2   715    // sum_{l<10} (l+1)(2l+1)
#define NSQ2  1330   // sum_{l<10} (2l+1)^2  (full, for dh10)
#define MR1   31
#define MR2   19

__device__ __forceinline__ int offsq(int l){ return l*(4*l*l-1)/3; }
// half offset: sum_{l'<l} (l'+1)(2l'+1)
__device__ __forceinline__ int hoff(int l){
    return ((l-1)*l*(2*l-1))/3 + (3*(l-1)*l)/2 + l;
}
__device__ __forceinline__ void unpack_h(int p, int &l, int &m, int &jn){
    l=0; while (p >= (l+1)*(2*l+1)){ p -= (l+1)*(2*l+1); l++; }
    m = p/(2*l+1); jn = p%(2*l+1);
}

// ---------------- scratch ----------------
__device__ float  g_img[BATCH*NA60*NA60];
__device__ float2 g_Ga [BATCH*NA60*MR1];
__device__ float2 g_X1 [BATCH*NC1];
__device__ float2 g_Wh1[F0*MR1];
__device__ float2 g_Y1 [F0*NC1];
__device__ float  g_h1 [BATCH*F0*N32*N32*N32];       // 104.9 MB
__device__ float  g_bn1a[F0], g_bn1bv[F0];
__device__ float2 g_G2h[BATCH*F0*N32*10*MR2];        // m>=0 half: 38.9 MB
__device__ float2 g_X2h[BATCH*F0*NH2];
__device__ float2 g_Wh2[F0*F1*MR2];
__device__ float2 g_Aah[BATCH*F0*NH2];
__device__ float2 g_Z2h[BATCH*F1*NH2];
__device__ float  g_h2 [BATCH*F1*N20*N20*N20];
__device__ float  g_bn2a[F1], g_bn2bv[F1];
__device__ float  g_feat[BATCH*F1];
__device__ double2 g_s1p[BATCH*F0];
__device__ double2 g_s2p[BATCH*F1];

// ---------------- tables ----------------
__device__ float g_d16h  [N32*NH1];    // raw d^l(m>=0 half) at dh(16) betas; l<10 prefix used by k_x2
__device__ float g_d10h  [N20*NH2];
__device__ float g_dh10  [NSQ2];       // full d at pi/2 (k_a)
__device__ float g_dcol30[NA60*NC1];
__device__ float g_dhcol [NC1];
__device__ float g_qw30[NA60], g_qw16[N32], g_qw10[N20];

// ============ Wigner-d: term-ratio recurrence (double) ============
__device__ double d_ipow(double x, int n){ double r=1.0; for(int i=0;i<n;i++) r*=x; return r; }

__device__ double d_wig(int l, int mp, int m, double beta, const double* f){
    if (l == 0) return 1.0;
    double cb = cos(0.5*beta), sb = sin(0.5*beta);
    int smin = max(0, m-mp);
    int smax = min(l+m, l-mp);
    double pref = sqrt(f[l+mp]*f[l-mp]*f[l+m]*f[l-m]);
    double term = d_ipow(cb, 2*l+m-mp-2*smin) * d_ipow(sb, mp-m+2*smin)
                / (f[l+m-smin]*f[smin]*f[mp-m+smin]*f[l-mp-smin]);
    if ((mp-m+smin)&1) term = -term;
    double acc = term;
    double r2 = (sb*sb)/(cb*cb);
    for (int s=smin; s<smax; s++){
        term *= -r2 * (double)((l+m-s)*(l-mp-s)) / ((double)(s+1)*(double)(mp-m+s+1));
        acc += term;
    }
    return pref*acc;
}

// ============ merged setup ============
#define T0 (N32*NH1)
#define T1 (N20*NH2)
#define T2 (NSQ2)
#define T3 (NA60*NC1)
#define T4 (NC1)
#define T5 (112)
#define TSETUP (T0+T1+T2+T3+T4+T5)

__global__ void k_setup(){
    __shared__ double f[32];
    if (threadIdx.x == 0){ f[0]=1.0; for (int i=1;i<32;i++) f[i]=f[i-1]*(double)i; }
    __syncthreads();
    int tid = blockIdx.x*blockDim.x + threadIdx.x;
    if (tid >= TSETUP) return;
    if (tid < T0){
        int k = tid/NH1, p = tid%NH1;
        int l,m,jn; unpack_h(p,l,m,jn);
        double beta = PI*(2*k+1)/64.0;
        g_d16h[tid] = (float)d_wig(l, m, jn-l, beta, f);
        return;
    }
    tid -= T0;
    if (tid < T1){
        int k = tid/NH2, p = tid%NH2;
        int l,m,jn; unpack_h(p,l,m,jn);
        double beta = PI*(2*k+1)/40.0;
        g_d10h[tid] = (float)d_wig(l, m, jn-l, beta, f);
        return;
    }
    tid -= T1;
    if (tid < T2){
        int p = tid;
        int l=0; while (p >= (2*l+1)*(2*l+1)){ p -= (2*l+1)*(2*l+1); l++; }
        int jm = p/(2*l+1), jn = p%(2*l+1);
        g_dh10[tid] = (float)d_wig(l, jm-l, jn-l, 0.5*PI, f);
        return;
    }
    tid -= T2;
    if (tid < T3){
        int k = tid/NC1, p = tid%NC1;
        int l=0; while ((l+1)*(l+1) <= p) l++;
        int jm = p - l*l;
        double beta = PI*(2*k+1)/120.0;
        g_dcol30[tid] = (float)d_wig(l, jm-l, 0, beta, f);
        return;
    }
    tid -= T3;
    if (tid < T4){
        int p = tid;
        int l=0; while ((l+1)*(l+1) <= p) l++;
        int jm = p - l*l;
        g_dhcol[tid] = (float)d_wig(l, jm-l, 0, 0.5*PI, f);
        return;
    }
    tid -= T4;
    {
        int bgrid, k; float* out;
        if (tid < 60){ bgrid=30; out=g_qw30; k=tid; }
        else if (tid < 92){ bgrid=16; out=g_qw16; k=tid-60; }
        else { bgrid=10; out=g_qw10; k=tid-92; }
        double beta = PI*(2*k+1)/(4.0*bgrid);
        double s = 0.0;
        for (int j=0;j<bgrid;j++)
            s += sin((double)(2*k+1)*(2*j+1)*PI/(4.0*bgrid))/(double)(2*j+1);
        out[k] = (float)((2.0/bgrid)*sin(beta)*s);
    }
}

// ============ pipeline ============
__global__ void k_zero_img(){
    int i = blockIdx.x*blockDim.x + threadIdx.x;
    if (i < BATCH*NA60*NA60) g_img[i] = 0.0f;
}

__global__ void k_project(const float* __restrict__ x){
    int tid = blockIdx.x*blockDim.x + threadIdx.x;
    if (tid >= BATCH*NPTS) return;
    int b = tid/NPTS, p = tid%NPTS;
    float xx = x[b*3*NPTS + 0*NPTS + p];
    float yy = x[b*3*NPTS + 1*NPTS + p];
    float zz = x[b*3*NPTS + 2*NPTS + p];
    float r  = sqrtf(xx*xx + yy*yy + zz*zz);
    float rc = fmaxf(r, 1e-8f);
    float cz = fminf(fmaxf(zz/rc, -1.0f), 1.0f);
    float beta  = acosf(cz);
    float alpha = atan2f(yy, xx);
    if (alpha < 0.0f) alpha += 2.0f*(float)PI;
    int bi = (int)(beta/(float)PI*60.0f);          bi = min(max(bi,0),59);
    int ai = (int)(alpha/(2.0f*(float)PI)*60.0f);  ai = min(max(ai,0),59);
    atomicMax((int*)&g_img[(b*NA60+bi)*NA60 + ai], __float_as_int(r));
}

__global__ void k_ga(){
    __shared__ float2 tab[NA60];
    int t = threadIdx.x;
    if (t < NA60){ double s,c; sincospi(-2.0*t/60.0,&s,&c); tab[t]=make_float2((float)c,(float)s); }
    __syncthreads();
    int tid = blockIdx.x*blockDim.x + t;
    if (tid >= BATCH*NA60*MR1) return;
    int j = tid % MR1; int bk = tid / MR1;
    int m = j - 15;
    int inc = ((m%60)+60)%60;
    float sr=0.0f, si=0.0f;
    const float* row = g_img + bk*NA60;
    int idx=0;
    #pragma unroll 4
    for (int a=0;a<NA60;a++){
        float2 w = tab[idx];
        float v = row[a];
        sr += v*w.x; si += v*w.y;
        idx += inc; if (idx>=60) idx-=60;
    }
    g_Ga[tid] = make_float2(sr,si);
}

__global__ void k_x1(){
    int tid = blockIdx.x*blockDim.x + threadIdx.x;
    if (tid >= BATCH*NC1) return;
    int p = tid % NC1, b = tid / NC1;
    int l=0; while ((l+1)*(l+1) <= p) l++;
    int m = (p - l*l) - l;
    float ar=0.0f, ai=0.0f;
    for (int k=0;k<NA60;k++){
        float wd = g_qw30[k]*g_dcol30[k*NC1 + p];
        float2 ga = g_Ga[(b*NA60+k)*MR1 + (m+15)];
        ar += wd*ga.x; ai += wd*ga.y;
    }
    float sc = (float)(2.0*PI/60.0);
    g_X1[tid] = make_float2(ar*sc, ai*sc);
}

__global__ void k_wh1(const float* __restrict__ w_s2){
    __shared__ float2 tab[NA60];
    int t = threadIdx.x;
    if (t < NA60){ double s,c; sincospi(-2.0*t/60.0,&s,&c); tab[t]=make_float2((float)c,(float)s); }
    __syncthreads();
    int tid = blockIdx.x*blockDim.x + t;
    if (tid >= F0*MR1) return;
    int j = tid % MR1, o = tid / MR1;
    int m = j - 15;
    int inc = ((m%60)+60)%60;
    float sr=0.0f, si=0.0f;
    const float* w = w_s2 + o*NA60;
    int idx=0;
    for (int p=0;p<NA60;p++){
        float2 e = tab[idx];
        sr += w[p]*e.x; si += w[p]*e.y;
        idx += inc; if (idx>=60) idx-=60;
    }
    g_Wh1[tid] = make_float2(sr,si);
}

__global__ void k_y1(){
    int tid = blockIdx.x*blockDim.x + threadIdx.x;
    if (tid >= F0*NC1) return;
    int p = tid % NC1, o = tid / NC1;
    int l=0; while ((l+1)*(l+1) <= p) l++;
    int m = (p - l*l) - l;
    float d = g_dhcol[p] * (1.0f/60.0f);
    float2 w = g_Wh1[o*MR1 + (m+15)];
    g_Y1[tid] = make_float2(d*w.x, d*w.y);
}

// layer-1 synthesis, Hermitian half-spectrum, persistent over k. One block per (b,o).
__global__ void k_syn1(){
    __shared__ float2 Zv [NH1];          // (2l+1)*X[l,m]*conj(Y[l,n]), m>=0
    __shared__ float2 Msh[16*MR1];       // rows m=0..15, cols n=-15..15
    __shared__ float2 Tsh[16*N32];
    __shared__ float2 Xsh[NC1], Ysh[NC1];
    __shared__ float2 ctab[N32];
    __shared__ double red[256], red2[256];
    int bo = blockIdx.x;
    int o = bo % F0, b = bo / F0;
    int t = threadIdx.x;
    for (int i=t;i<NC1;i+=256){ Xsh[i]=g_X1[b*NC1+i]; Ysh[i]=g_Y1[o*NC1+i]; }
    if (t < N32){ double s,c; sincospi(2.0*t/32.0,&s,&c); ctab[t]=make_float2((float)c,(float)s); }
    __syncthreads();
    for (int ph=t; ph<NH1; ph+=256){
        int l,m,jn; unpack_h(ph,l,m,jn);
        float2 xv = Xsh[l*l + m+l];
        float2 yv = Ysh[l*l + jn];
        float w = (float)(2*l+1);
        Zv[ph] = make_float2(w*(xv.x*yv.x + xv.y*yv.y),
                             w*(xv.y*yv.x - xv.x*yv.y));
    }
    double ls=0.0, ls2=0.0;
    float* hbase = g_h1 + (size_t)bo * 32768;
    for (int k=0;k<N32;k++){
        __syncthreads();
        const float* dk = g_d16h + k*NH1;
        for (int e=t; e<16*MR1; e+=256){
            int m = e/MR1, jn = e%MR1;
            int n = jn-15;
            int lmin = max(m, abs(n));
            float ar=0.0f, ai=0.0f;
            int off = hoff(lmin);
            for (int l=lmin; l<L1MAX; l++){
                int idx = off + m*(2*l+1) + (n+l);
                float w = dk[idx];
                float2 z = Zv[idx];
                ar += w*z.x; ai += w*z.y;
                off += (l+1)*(2*l+1);
            }
            Msh[e] = make_float2(ar, ai);
        }
        __syncthreads();
        {   // T[m,g] = sum_n e^{ign} M[m,n]; rows m>=1 pre-doubled
            int g = t & 31, warp = t >> 5;
            for (int m=warp; m<16; m+=8){
                float tr=0.0f, ti=0.0f;
                int idx = (g*17) & 31;
                #pragma unroll
                for (int jn=0;jn<MR1;jn++){
                    float2 w = ctab[idx];
                    float2 mm = Msh[m*MR1+jn];
                    tr += mm.x*w.x - mm.y*w.y;
                    ti += mm.x*w.y + mm.y*w.x;
                    idx = (idx+g) & 31;
                }
                float sc = (m>0) ? 2.0f : 1.0f;
                Tsh[m*N32+g] = make_float2(sc*tr, sc*ti);
            }
        }
        __syncthreads();
        {   // H[a,g] = T0 + sum_{m=1..15} Re(e^{iam} * 2*T[m,g])
            float* hout = hbase + k*1024;
            int g = t & 31, warp = t >> 5;
            for (int a=warp; a<N32; a+=8){
                float acc = Tsh[g].x;
                int cur = a;
                #pragma unroll
                for (int m=1;m<16;m++){
                    float2 w = ctab[cur];
                    float2 tv = Tsh[m*N32+g];
                    acc += tv.x*w.x - tv.y*w.y;
                    cur = (cur+a) & 31;
                }
                hout[a*32+g] = acc;
                ls += acc; ls2 += (double)acc*acc;
            }
        }
    }
    red[t]=ls; red2[t]=ls2; __syncthreads();
    for (int st=128; st>0; st>>=1){ if (t<st){ red[t]+=red[t+st]; red2[t]+=red2[t+st]; } __syncthreads(); }
    if (t==0) g_s1p[bo] = make_double2(red[0], red2[0]);
}

__global__ void k_bn1fin(const float* __restrict__ gw, const float* __restrict__ gb){
    int o = blockIdx.x; int t = threadIdx.x;
    double s=0.0, s2=0.0;
    if (t < BATCH){ double2 p = g_s1p[t*F0+o]; s=p.x; s2=p.y; }
    for (int st=4; st>0; st>>=1){
        s  += __shfl_down_sync(0xffffffffu, s,  st);
        s2 += __shfl_down_sync(0xffffffffu, s2, st);
    }
    if (t==0){
        double N = (double)BATCH*32768.0;
        double mu = s/N;
        double var = s2/N - mu*mu;
        float a = gw[o] * (float)rsqrt(var + 1e-5);
        g_bn1a[o]=a; g_bn1bv[o]= gb[o] - (float)mu * a;
    }
}

// fused BN+relu + truncated half fft2 (m>=0)
__global__ void k_g2(){
    __shared__ float  hsh[N32*N32];
    __shared__ float2 Ush[10*N32];
    __shared__ float2 ctab[N32];
    int bid = blockIdx.x;                    // (b*F0+c)*32 + k
    int t = threadIdx.x;
    int c = (bid >> 5) % F0;
    float a1 = g_bn1a[c], b1 = g_bn1bv[c];
    const float* hin = g_h1 + (size_t)bid*1024;
    for (int i=t;i<1024;i+=256){ float v = hin[i]*a1 + b1; hsh[i] = v>0.0f ? v : 0.0f; }
    if (t<N32){ double s,cc; sincospi(2.0*t/32.0,&s,&cc); ctab[t]=make_float2((float)cc,(float)s); }
    __syncthreads();
    {   // U[m,g] = sum_a e^{-iam} h[a,g], m=0..9
        int g = t & 31, warp = t >> 5;
        for (int m=warp; m<10; m+=8){
            float ur=0.0f, ui=0.0f;
            int idx=0, inc=(32-m)&31;
            #pragma unroll
            for (int a=0;a<N32;a++){
                float2 w = ctab[idx];
                float v = hsh[a*32+g];
                ur += v*w.x; ui += v*w.y;
                idx = (idx+inc)&31;
            }
            Ush[m*N32+g]=make_float2(ur,ui);
        }
    }
    __syncthreads();
    float2* gout = g_G2h + (size_t)bid*(10*MR2);
    for (int e=t; e<10*MR2; e+=256){
        int m=e/MR2, jn=e%MR2, n=jn-9;
        float gr=0.0f, gi=0.0f;
        int idx=0, inc=(-n)&31;
        #pragma unroll
        for (int g=0; g<N32; g++){
            float2 w = ctab[idx];
            float2 u = Ush[m*N32+g];
            gr += u.x*w.x - u.y*w.y;
            gi += u.x*w.y + u.y*w.x;
            idx=(idx+inc)&31;
        }
        gout[e]=make_float2(gr,gi);
    }
}

// so3_fft beta contraction on half spectrum (m>=0)
__global__ void k_x2(){
    int tid = blockIdx.x*blockDim.x + threadIdx.x;
    if (tid >= BATCH*F0*NH2) return;
    int p = tid % NH2; int bc = tid / NH2;
    int l,m,jn; unpack_h(p,l,m,jn);
    int col = (jn - l) + 9;
    float ar=0.0f, ai=0.0f;
    const float2* G = g_G2h + (size_t)bc*N32*(10*MR2);
    #pragma unroll 4
    for (int k=0;k<N32;k++){
        float wd = g_qw16[k]*g_d16h[k*NH1 + p];   // l<10 prefix of half-16 table
        float2 gg = G[k*(10*MR2) + m*MR2 + col];
        ar += wd*gg.x; ai += wd*gg.y;
    }
    float sc = (float)((2.0*PI/32.0)*(2.0*PI/32.0));
    g_X2h[tid] = make_float2(ar*sc, ai*sc);
}

__global__ void k_wh2(const float* __restrict__ w_so3){
    __shared__ float2 tab[N32];
    int t = threadIdx.x;
    if (t<N32){ double s,c; sincospi(-2.0*t/32.0,&s,&c); tab[t]=make_float2((float)c,(float)s); }
    __syncthreads();
    int tid = blockIdx.x*blockDim.x + t;
    if (tid >= F0*F1*MR2) return;
    int j = tid % MR2; int io = tid / MR2;
    int m = j - 9;
    int inc = m & 31;
    float sr=0.0f, si=0.0f;
    const float* w = w_so3 + io*N32;
    int idx=0;
    #pragma unroll
    for (int p=0;p<N32;p++){
        float2 e = tab[idx];
        sr += w[p]*e.x; si += w[p]*e.y;
        idx=(idx+inc)&31;
    }
    g_Wh2[tid] = make_float2(sr*(1.0f/32.0f), si*(1.0f/32.0f));
}

// A[l,m,n] = sum_k X2[l,m,k] dh[n,k]  (m>=0 rows)
__global__ void k_a(){
    int tid = blockIdx.x*blockDim.x + threadIdx.x;
    if (tid >= BATCH*F0*NH2) return;
    int p = tid % NH2; int bi = tid / NH2;
    int l,m,jn; unpack_h(p,l,m,jn);
    int w = 2*l+1;
    const float2* X = g_X2h + (size_t)bi*NH2 + hoff(l) + m*w;
    const float*  dd = g_dh10 + offsq(l) + jn*w;
    float ar=0.0f, ai=0.0f;
    for (int jk=0; jk<w; jk++){
        float d = dd[jk]; float2 xv = X[jk];
        ar += d*xv.x; ai += d*xv.y;
    }
    g_Aah[tid] = make_float2(ar,ai);
}

// Z2 half with 4-way o tiling
__global__ void k_z2(){
    int tid = blockIdx.x*blockDim.x + threadIdx.x;
    if (tid >= BATCH*25*NH2) return;
    int p = tid % NH2; int rest = tid / NH2;
    int oq = rest % 25; int b = rest / 25;
    int l,m,jn; unpack_h(p,l,m,jn);
    int jw = (jn - l) + 9;
    float ar0=0,ai0=0,ar1=0,ai1=0,ar2=0,ai2=0,ar3=0,ai3=0;
    const float2* A = g_Aah + (size_t)b*F0*NH2 + p;
    const float2* W = g_Wh2 + oq*MR2 + jw;
    #pragma unroll 2
    for (int i=0;i<F0;i++){
        float2 a = A[(size_t)i*NH2];
        const float2* Wi = W + (size_t)i*F1*MR2;
        float2 w0 = Wi[0*25*MR2];
        float2 w1 = Wi[1*25*MR2];
        float2 w2 = Wi[2*25*MR2];
        float2 w3 = Wi[3*25*MR2];
        ar0 += a.x*w0.x + a.y*w0.y;  ai0 += a.y*w0.x - a.x*w0.y;
        ar1 += a.x*w1.x + a.y*w1.y;  ai1 += a.y*w1.x - a.x*w1.y;
        ar2 += a.x*w2.x + a.y*w2.y;  ai2 += a.y*w2.x - a.x*w2.y;
        ar3 += a.x*w3.x + a.y*w3.y;  ai3 += a.y*w3.x - a.x*w3.y;
    }
    size_t base = (size_t)(b*F1)*NH2 + p;
    g_Z2h[base + (size_t)(oq   )*NH2] = make_float2(ar0,ai0);
    g_Z2h[base + (size_t)(oq+25)*NH2] = make_float2(ar1,ai1);
    g_Z2h[base + (size_t)(oq+50)*NH2] = make_float2(ar2,ai2);
    g_Z2h[base + (size_t)(oq+75)*NH2] = make_float2(ar3,ai3);
}

// layer-2 synthesis, half spectrum, persistent over k. One block per (b,o).
__global__ void k_syn2(){
    __shared__ float2 Zsh[NH2];
    __shared__ float2 Msh[10*MR2];
    __shared__ float2 Tsh[10*N20];
    __shared__ float2 ctab[N20];
    __shared__ double red[256], red2[256];
    int bo = blockIdx.x;
    int t = threadIdx.x;
    if (t < N20){ double s,c; sincospi(2.0*t/20.0,&s,&c); ctab[t]=make_float2((float)c,(float)s); }
    for (int ph=t; ph<NH2; ph+=256){
        int l,m,jn; unpack_h(ph,l,m,jn);
        float2 z = g_Z2h[(size_t)bo*NH2 + ph];
        float w = (float)(2*l+1);
        Zsh[ph] = make_float2(w*z.x, w*z.y);
    }
    double ls=0.0, ls2=0.0;
    float* hbase = g_h2 + (size_t)bo*8000;
    for (int k=0;k<N20;k++){
        __syncthreads();
        const float* dk = g_d10h + k*NH2;
        for (int e=t; e<10*MR2; e+=256){
            int m=e/MR2, jn=e%MR2;
            int n=jn-9;
            int lmin = max(m, abs(n));
            float ar=0.0f, ai=0.0f;
            int off = hoff(lmin);
            for (int l=lmin; l<L2MAX; l++){
                int idx = off + m*(2*l+1) + (n+l);
                float w = dk[idx];
                float2 z = Zsh[idx];
                ar += w*z.x; ai += w*z.y;
                off += (l+1)*(2*l+1);
            }
            Msh[e] = make_float2(ar,ai);
        }
        __syncthreads();
        {
            int g = t % 20, row = t / 20;        // 240 active threads: rows 0..11
            if (row < 10){
                float tr=0.0f, ti=0.0f;
                int idx=(g*11)%20, inc=g;
                #pragma unroll
                for (int jn=0;jn<MR2;jn++){
                    float2 w = ctab[idx];
                    float2 mm = Msh[row*MR2+jn];
                    tr += mm.x*w.x - mm.y*w.y;
                    ti += mm.x*w.y + mm.y*w.x;
                    idx += inc; if (idx>=20) idx-=20;
                }
                float sc = (row>0)?2.0f:1.0f;
                Tsh[row*N20+g] = make_float2(sc*tr, sc*ti);
            }
        }
        __syncthreads();
        {
            float* hout = hbase + k*400;
            for (int e=t; e<400; e+=256){
                int a=e/N20, g=e%N20;
                float acc = Tsh[g].x;
                int cur = a % 20;
                #pragma unroll
                for (int m=1;m<10;m++){
                    float2 w = ctab[cur];
                    float2 tv = Tsh[m*N20+g];
                    acc += tv.x*w.x - tv.y*w.y;
                    cur += a; if (cur>=20) cur-=20;
                }
                hout[e] = acc;
                ls += acc; ls2 += (double)acc*acc;
            }
        }
    }
    red[t]=ls; red2[t]=ls2; __syncthreads();
    for (int st=128; st>0; st>>=1){ if (t<st){ red[t]+=red[t+st]; red2[t]+=red2[t+st]; } __syncthreads(); }
    if (t==0) g_s2p[bo] = make_double2(red[0], red2[0]);
}

__global__ void k_bn2fin(const float* __restrict__ gw, const float* __restrict__ gb){
    int o = blockIdx.x; int t = threadIdx.x;
    double s=0.0, s2=0.0;
    if (t < BATCH){ double2 p = g_s2p[t*F1+o]; s=p.x; s2=p.y; }
    for (int st=4; st>0; st>>=1){
        s  += __shfl_down_sync(0xffffffffu, s,  st);
        s2 += __shfl_down_sync(0xffffffffu, s2, st);
    }
    if (t==0){
        double N = (double)BATCH*8000.0;
        double mu = s/N;
        double var = s2/N - mu*mu;
        float a = gw[o] * (float)rsqrt(var + 1e-5);
        g_bn2a[o]=a; g_bn2bv[o]= gb[o] - (float)mu * a;
    }
}

__global__ void k_integrate(){
    int bf = blockIdx.x;
    int f = bf % F1;
    int t = threadIdx.x;
    float a = g_bn2a[f], bb = g_bn2bv[f];
    double s = 0.0;
    const float* h = g_h2 + (size_t)bf*8000;
    for (int idx=t; idx<8000; idx+=256){
        int k = idx/400;
        float v = h[idx]*a + bb;
        v = v>0.0f ? v : 0.0f;
        s += (double)v * (double)g_qw10[k];
    }
    __shared__ double sh[256];
    sh[t]=s; __syncthreads();
    for (int st=128; st>0; st>>=1){ if (t<st) sh[t]+=sh[t+st]; __syncthreads(); }
    if (t==0){
        double sc = (2.0*PI/20.0)*(2.0*PI/20.0);
        g_feat[bf] = (float)(sh[0]*sc);
    }
}

__global__ void k_lin(const float* __restrict__ lw, const float* __restrict__ lb,
                      float* __restrict__ out){
    int tid = blockIdx.x*blockDim.x + threadIdx.x;
    if (tid >= BATCH*NCLS) return;
    int c = tid % NCLS, b = tid / NCLS;
    float acc = lb[c];
    for (int f=0; f<F1; f++) acc += g_feat[b*F1+f]*lw[f*NCLS+c];
    out[tid] = acc;
}

// ================= host =================
extern "C" void kernel_launch(void* const* d_in, const int* in_sizes, int n_in,
                              void* d_out, int out_size){
    const float* x     = (const float*)d_in[0];
    const float* w_s2  = (const float*)d_in[1];
    const float* bn1g  = (const float*)d_in[3];
    const float* bn1b  = (const float*)d_in[4];
    const float* w_so3 = (const float*)d_in[5];
    const float* bn2g  = (const float*)d_in[7];
    const float* bn2b  = (const float*)d_in[8];
    const float* linw  = (const float*)d_in[9];
    const float* linb  = (const float*)d_in[10];
    float* out = (float*)d_out;

    k_setup<<<(TSETUP+255)/256,256>>>();
    k_zero_img<<<(BATCH*NA60*NA60+255)/256,256>>>();
    k_project<<<(BATCH*NPTS+255)/256,256>>>(x);
    k_ga<<<(BATCH*NA60*MR1+255)/256,256>>>();
    k_x1<<<(BATCH*NC1+255)/256,256>>>();
    k_wh1<<<(F0*MR1+255)/256,256>>>(w_s2);
    k_y1<<<(F0*NC1+255)/256,256>>>();
    k_syn1<<<BATCH*F0,256>>>();
    k_bn1fin<<<F0,32>>>(bn1g, bn1b);
    k_g2<<<BATCH*F0*N32,256>>>();
    k_x2<<<(BATCH*F0*NH2+255)/256,256>>>();
    k_wh2<<<(F0*F1*MR2+255)/256,256>>>(w_so3);
    k_a<<<(BATCH*F0*NH2+255)/256,256>>>();
    k_z2<<<(BATCH*25*NH2+255)/256,256>>>();
    k_syn2<<<BATCH*F1,256>>>();
    k_bn2fin<<<F1,32>>>(bn2g, bn2b);
    k_integrate<<<BATCH*F1,256>>>();
    k_lin<<<(BATCH*NCLS+255)/256,256>>>(linw, linb, out);
}

// round 8
// speedup vs baseline: 3.3096x; 1.2094x over previous
#include <cuda_runtime.h>
#include <math.h>

#define PI 3.14159265358979323846

#define BATCH 8
#define NPTS  1024
#define F0    100
#define F1    100
#define NCLS  40

#define NA60  60
#define L1MAX 16
#define N32   32
#define L2MAX 10
#define N20   20

#define NC1   256
#define NH1   2856   // sum_{l<16} (l+1)(2l+1)  (m>=0 half)
#define NH2   715    // sum_{l<10} (l+1)(2l+1)
#define NSQ2  1330   // sum_{l<10} (2l+1)^2  (full, for dh10)
#define MR1   31
#define MR2   19

__device__ __forceinline__ int offsq(int l){ return l*(4*l*l-1)/3; }
__device__ __forceinline__ int hoff(int l){
    return ((l-1)*l*(2*l-1))/3 + (3*(l-1)*l)/2 + l;
}
__device__ __forceinline__ void unpack_h(int p, int &l, int &m, int &jn){
    l=0; while (p >= (l+1)*(2*l+1)){ p -= (l+1)*(2*l+1); l++; }
    m = p/(2*l+1); jn = p%(2*l+1);
}

// ---------------- scratch ----------------
__device__ float  g_img[BATCH*NA60*NA60];
__device__ float2 g_Ga [BATCH*NA60*MR1];
__device__ float2 g_X1 [BATCH*NC1];
__device__ float2 g_Wh1[F0*MR1];
__device__ float2 g_Y1 [F0*NC1];
__device__ float  g_h1 [BATCH*F0*N32*N32*N32];
__device__ float  g_bn1a[F0], g_bn1bv[F0];
__device__ float2 g_Wh2[F0*F1*MR2];
__device__ float2 g_Aah[BATCH*F0*NH2];
__device__ float2 g_Z2h[BATCH*F1*NH2];
__device__ float  g_h2 [BATCH*F1*N20*N20*N20];
__device__ float  g_bn2a[F1], g_bn2bv[F1];
__device__ float  g_feat[BATCH*F1];
__device__ double2 g_s1p[BATCH*F0];
__device__ double2 g_s2p[BATCH*F1];

// ---------------- tables ----------------
__device__ float g_d16h  [N32*NH1];
__device__ float g_d10h  [N20*NH2];
__device__ float g_dh10  [NSQ2];
__device__ float g_dcol30[NA60*NC1];
__device__ float g_dhcol [NC1];
__device__ float g_qw30[NA60], g_qw16[N32], g_qw10[N20];

// ============ Wigner-d ============
__device__ double d_ipow(double x, int n){ double r=1.0; for(int i=0;i<n;i++) r*=x; return r; }

__device__ double d_wig(int l, int mp, int m, double beta, const double* f){
    if (l == 0) return 1.0;
    double cb = cos(0.5*beta), sb = sin(0.5*beta);
    int smin = max(0, m-mp);
    int smax = min(l+m, l-mp);
    double pref = sqrt(f[l+mp]*f[l-mp]*f[l+m]*f[l-m]);
    double term = d_ipow(cb, 2*l+m-mp-2*smin) * d_ipow(sb, mp-m+2*smin)
                / (f[l+m-smin]*f[smin]*f[mp-m+smin]*f[l-mp-smin]);
    if ((mp-m+smin)&1) term = -term;
    double acc = term;
    double r2 = (sb*sb)/(cb*cb);
    for (int s=smin; s<smax; s++){
        term *= -r2 * (double)((l+m-s)*(l-mp-s)) / ((double)(s+1)*(double)(mp-m+s+1));
        acc += term;
    }
    return pref*acc;
}

#define T0c (N32*NH1)
#define T1c (N20*NH2)
#define T2c (NSQ2)
#define T3c (NA60*NC1)
#define T4c (NC1)
#define T5c (112)
#define TSETUP (T0c+T1c+T2c+T3c+T4c+T5c)

__global__ void k_setup(){
    __shared__ double f[32];
    if (threadIdx.x == 0){ f[0]=1.0; for (int i=1;i<32;i++) f[i]=f[i-1]*(double)i; }
    __syncthreads();
    int tid = blockIdx.x*blockDim.x + threadIdx.x;
    if (tid >= TSETUP) return;
    if (tid < T0c){
        int k = tid/NH1, p = tid%NH1;
        int l,m,jn; unpack_h(p,l,m,jn);
        double beta = PI*(2*k+1)/64.0;
        g_d16h[tid] = (float)d_wig(l, m, jn-l, beta, f);
        return;
    }
    tid -= T0c;
    if (tid < T1c){
        int k = tid/NH2, p = tid%NH2;
        int l,m,jn; unpack_h(p,l,m,jn);
        double beta = PI*(2*k+1)/40.0;
        g_d10h[tid] = (float)d_wig(l, m, jn-l, beta, f);
        return;
    }
    tid -= T1c;
    if (tid < T2c){
        int p = tid;
        int l=0; while (p >= (2*l+1)*(2*l+1)){ p -= (2*l+1)*(2*l+1); l++; }
        int jm = p/(2*l+1), jn = p%(2*l+1);
        g_dh10[tid] = (float)d_wig(l, jm-l, jn-l, 0.5*PI, f);
        return;
    }
    tid -= T2c;
    if (tid < T3c){
        int k = tid/NC1, p = tid%NC1;
        int l=0; while ((l+1)*(l+1) <= p) l++;
        int jm = p - l*l;
        double beta = PI*(2*k+1)/120.0;
        g_dcol30[tid] = (float)d_wig(l, jm-l, 0, beta, f);
        return;
    }
    tid -= T3c;
    if (tid < T4c){
        int p = tid;
        int l=0; while ((l+1)*(l+1) <= p) l++;
        int jm = p - l*l;
        g_dhcol[tid] = (float)d_wig(l, jm-l, 0, 0.5*PI, f);
        return;
    }
    tid -= T4c;
    {
        int bgrid, k; float* out;
        if (tid < 60){ bgrid=30; out=g_qw30; k=tid; }
        else if (tid < 92){ bgrid=16; out=g_qw16; k=tid-60; }
        else { bgrid=10; out=g_qw10; k=tid-92; }
        double beta = PI*(2*k+1)/(4.0*bgrid);
        double s = 0.0;
        for (int j=0;j<bgrid;j++)
            s += sin((double)(2*k+1)*(2*j+1)*PI/(4.0*bgrid))/(double)(2*j+1);
        out[k] = (float)((2.0/bgrid)*sin(beta)*s);
    }
}

// ============ pipeline ============
__global__ void k_zero_img(){
    int i = blockIdx.x*blockDim.x + threadIdx.x;
    if (i < BATCH*NA60*NA60) g_img[i] = 0.0f;
}

__global__ void k_project(const float* __restrict__ x){
    int tid = blockIdx.x*blockDim.x + threadIdx.x;
    if (tid >= BATCH*NPTS) return;
    int b = tid/NPTS, p = tid%NPTS;
    float xx = x[b*3*NPTS + 0*NPTS + p];
    float yy = x[b*3*NPTS + 1*NPTS + p];
    float zz = x[b*3*NPTS + 2*NPTS + p];
    float r  = sqrtf(xx*xx + yy*yy + zz*zz);
    float rc = fmaxf(r, 1e-8f);
    float cz = fminf(fmaxf(zz/rc, -1.0f), 1.0f);
    float beta  = acosf(cz);
    float alpha = atan2f(yy, xx);
    if (alpha < 0.0f) alpha += 2.0f*(float)PI;
    int bi = (int)(beta/(float)PI*60.0f);          bi = min(max(bi,0),59);
    int ai = (int)(alpha/(2.0f*(float)PI)*60.0f);  ai = min(max(ai,0),59);
    atomicMax((int*)&g_img[(b*NA60+bi)*NA60 + ai], __float_as_int(r));
}

__global__ void k_ga(){
    __shared__ float2 tab[NA60];
    int t = threadIdx.x;
    if (t < NA60){ double s,c; sincospi(-2.0*t/60.0,&s,&c); tab[t]=make_float2((float)c,(float)s); }
    __syncthreads();
    int tid = blockIdx.x*blockDim.x + t;
    if (tid >= BATCH*NA60*MR1) return;
    int j = tid % MR1; int bk = tid / MR1;
    int m = j - 15;
    int inc = ((m%60)+60)%60;
    float sr=0.0f, si=0.0f;
    const float* row = g_img + bk*NA60;
    int idx=0;
    #pragma unroll 4
    for (int a=0;a<NA60;a++){
        float2 w = tab[idx];
        float v = row[a];
        sr += v*w.x; si += v*w.y;
        idx += inc; if (idx>=60) idx-=60;
    }
    g_Ga[tid] = make_float2(sr,si);
}

__global__ void k_x1(){
    int tid = blockIdx.x*blockDim.x + threadIdx.x;
    if (tid >= BATCH*NC1) return;
    int p = tid % NC1, b = tid / NC1;
    int l=0; while ((l+1)*(l+1) <= p) l++;
    int m = (p - l*l) - l;
    float ar=0.0f, ai=0.0f;
    for (int k=0;k<NA60;k++){
        float wd = g_qw30[k]*g_dcol30[k*NC1 + p];
        float2 ga = g_Ga[(b*NA60+k)*MR1 + (m+15)];
        ar += wd*ga.x; ai += wd*ga.y;
    }
    float sc = (float)(2.0*PI/60.0);
    g_X1[tid] = make_float2(ar*sc, ai*sc);
}

__global__ void k_wh1(const float* __restrict__ w_s2){
    __shared__ float2 tab[NA60];
    int t = threadIdx.x;
    if (t < NA60){ double s,c; sincospi(-2.0*t/60.0,&s,&c); tab[t]=make_float2((float)c,(float)s); }
    __syncthreads();
    int tid = blockIdx.x*blockDim.x + t;
    if (tid >= F0*MR1) return;
    int j = tid % MR1, o = tid / MR1;
    int m = j - 15;
    int inc = ((m%60)+60)%60;
    float sr=0.0f, si=0.0f;
    const float* w = w_s2 + o*NA60;
    int idx=0;
    for (int p=0;p<NA60;p++){
        float2 e = tab[idx];
        sr += w[p]*e.x; si += w[p]*e.y;
        idx += inc; if (idx>=60) idx-=60;
    }
    g_Wh1[tid] = make_float2(sr,si);
}

__global__ void k_y1(){
    int tid = blockIdx.x*blockDim.x + threadIdx.x;
    if (tid >= F0*NC1) return;
    int p = tid % NC1, o = tid / NC1;
    int l=0; while ((l+1)*(l+1) <= p) l++;
    int m = (p - l*l) - l;
    float d = g_dhcol[p] * (1.0f/60.0f);
    float2 w = g_Wh1[o*MR1 + (m+15)];
    g_Y1[tid] = make_float2(d*w.x, d*w.y);
}

// layer-1 synthesis, half-spectrum + twiddle-pair factorization. Block per (b,o).
__global__ void k_syn1(){
    __shared__ float2 Zv [NH1];
    __shared__ float2 Msh[16*MR1];       // after PQ fold: [m][15+n]=P, [m][15-n]=Q
    __shared__ float2 Tsh[16*N32];
    __shared__ float2 Xsh[NC1], Ysh[NC1];
    __shared__ float2 ctab[N32];
    __shared__ double red[256], red2[256];
    int bo = blockIdx.x;
    int o = bo % F0, b = bo / F0;
    int t = threadIdx.x;
    for (int i=t;i<NC1;i+=256){ Xsh[i]=g_X1[b*NC1+i]; Ysh[i]=g_Y1[o*NC1+i]; }
    if (t < N32){ double s,c; sincospi(2.0*t/32.0,&s,&c); ctab[t]=make_float2((float)c,(float)s); }
    __syncthreads();
    for (int ph=t; ph<NH1; ph+=256){
        int l,m,jn; unpack_h(ph,l,m,jn);
        float2 xv = Xsh[l*l + m+l];
        float2 yv = Ysh[l*l + jn];
        float w = (float)(2*l+1);
        Zv[ph] = make_float2(w*(xv.x*yv.x + xv.y*yv.y),
                             w*(xv.y*yv.x - xv.x*yv.y));
    }
    double ls=0.0, ls2=0.0;
    float* hbase = g_h1 + (size_t)bo * 32768;
    for (int k=0;k<N32;k++){
        __syncthreads();
        const float* dk = g_d16h + k*NH1;
        // M-build (m>=0 half): 496 items
        for (int e=t; e<16*MR1; e+=256){
            int m = e / MR1, jn = e % MR1;
            int n = jn-15;
            int lmin = max(m, abs(n));
            float ar=0.0f, ai=0.0f;
            int off = hoff(lmin);
            for (int l=lmin; l<L1MAX; l++){
                int idx = off + m*(2*l+1) + (n+l);
                float w = dk[idx];
                float2 z = Zv[idx];
                ar += w*z.x; ai += w*z.y;
                off += (l+1)*(2*l+1);
            }
            Msh[e] = make_float2(ar, ai);
        }
        __syncthreads();
        // PQ fold in place: 240 items (m, n=1..15)
        for (int e=t; e<240; e+=256){
            int m = e/15, n = e%15 + 1;
            float2 Mp = Msh[m*MR1 + 15+n];
            float2 Mm = Msh[m*MR1 + 15-n];
            Msh[m*MR1 + 15+n] = make_float2(Mp.x+Mm.x, Mp.y+Mm.y);  // P
            Msh[m*MR1 + 15-n] = make_float2(Mp.x-Mm.x, Mp.y-Mm.y);  // Q
        }
        __syncthreads();
        // T-stage: 272 items (m=0..15, g=0..16), mirror to 32-g
        for (int e=t; e<272; e+=256){
            int m = e/17, g = e%17;
            float2 M0 = Msh[m*MR1 + 15];
            float tr1=M0.x, ti1=M0.y, tr2=M0.x, ti2=M0.y;
            int idx = g, step = g;
            #pragma unroll
            for (int n=1;n<16;n++){
                float2 w = ctab[idx];
                float2 P = Msh[m*MR1 + 15+n];
                float2 Q = Msh[m*MR1 + 15-n];
                float pcx = P.x*w.x, pcy = P.y*w.x;
                float qsx = Q.x*w.y, qsy = Q.y*w.y;
                tr1 += pcx - qsy; ti1 += pcy + qsx;
                tr2 += pcx + qsy; ti2 += pcy - qsx;
                idx = (idx+step)&31;
            }
            float sc = (m>0) ? 2.0f : 1.0f;
            Tsh[m*N32+g] = make_float2(sc*tr1, sc*ti1);
            if (g!=0 && g!=16) Tsh[m*N32+32-g] = make_float2(sc*tr2, sc*ti2);
        }
        __syncthreads();
        // H-stage: 544 items (a=0..16, g=0..31), mirror to 32-a
        float* hout = hbase + k*1024;
        for (int e=t; e<544; e+=256){
            int a = e >> 5, g = e & 31;
            float acc1 = Tsh[g].x, acc2 = acc1;
            int idx = a, step = a;
            #pragma unroll
            for (int m=1;m<16;m++){
                float2 w = ctab[idx];
                float2 tv = Tsh[m*N32+g];
                float p1 = tv.x*w.x, p2 = tv.y*w.y;
                acc1 += p1 - p2;
                acc2 += p1 + p2;
                idx = (idx+step)&31;
            }
            hout[a*32+g] = acc1;
            ls += acc1; ls2 += (double)acc1*acc1;
            if (a!=0 && a!=16){
                hout[(32-a)*32+g] = acc2;
                ls += acc2; ls2 += (double)acc2*acc2;
            }
        }
    }
    red[t]=ls; red2[t]=ls2; __syncthreads();
    for (int st=128; st>0; st>>=1){ if (t<st){ red[t]+=red[t+st]; red2[t]+=red2[t+st]; } __syncthreads(); }
    if (t==0) g_s1p[bo] = make_double2(red[0], red2[0]);
}

__global__ void k_bn1fin(const float* __restrict__ gw, const float* __restrict__ gb){
    int o = blockIdx.x; int t = threadIdx.x;
    double s=0.0, s2=0.0;
    if (t < BATCH){ double2 p = g_s1p[t*F0+o]; s=p.x; s2=p.y; }
    for (int st=4; st>0; st>>=1){
        s  += __shfl_down_sync(0xffffffffu, s,  st);
        s2 += __shfl_down_sync(0xffffffffu, s2, st);
    }
    if (t==0){
        double N = (double)BATCH*32768.0;
        double mu = s/N;
        double var = s2/N - mu*mu;
        float a = gw[o] * (float)rsqrt(var + 1e-5);
        g_bn1a[o]=a; g_bn1bv[o]= gb[o] - (float)mu * a;
    }
}

// fused BN+relu + half fft2 + beta-quadrature (X2) + pi/2 contraction (A).
// Block per (b,c), loops over k; X2 accumulated in registers.
__global__ void k_g2f(){
    __shared__ float  hsh[N32*N32];
    __shared__ float  Sph[15*N32], Smh[15*N32];
    __shared__ float2 Ush[10*N32];
    __shared__ float2 Gsh[10*MR2];
    __shared__ float2 ctab[N32];
    __shared__ float2 X2sh[NH2];
    int bc = blockIdx.x;
    int c = bc % F0;
    int t = threadIdx.x;
    float a1 = g_bn1a[c], b1 = g_bn1bv[c];
    if (t<N32){ double s,cc; sincospi(2.0*t/32.0,&s,&cc); ctab[t]=make_float2((float)cc,(float)s); }
    // per-thread spectral meta (<=3 entries)
    int pm[3], pcol[3];
    float axr[3]={0,0,0}, axi[3]={0,0,0};
    {
        int i=0;
        for (int p=t; p<NH2; p+=256){
            int l,m,jn; unpack_h(p,l,m,jn);
            pm[i]=m; pcol[i]=jn-l+9; i++;
        }
    }
    const float* hbase = g_h1 + (size_t)bc*32768;
    for (int k=0;k<N32;k++){
        __syncthreads();
        const float* hin = hbase + k*1024;
        for (int i=t;i<1024;i+=256){ float v = hin[i]*a1 + b1; hsh[i] = v>0.0f ? v : 0.0f; }
        __syncthreads();
        // fold a with 32-a: 480 items
        for (int e=t; e<480; e+=256){
            int a = e/32 + 1, g = e%32;
            float u = hsh[a*32+g], v = hsh[(32-a)*32+g];
            Sph[(a-1)*32+g] = u+v;
            Smh[(a-1)*32+g] = u-v;
        }
        __syncthreads();
        // U[m,g], m=0..9: 320 items
        for (int e=t; e<320; e+=256){
            int m = e/32, g = e%32;
            float h16 = hsh[16*32+g];
            float ur = hsh[g] + ((m&1) ? -h16 : h16);
            float ui = 0.0f;
            int idx = m&31, step = m;
            #pragma unroll
            for (int a=1;a<16;a++){
                float2 w = ctab[idx];
                ur += Sph[(a-1)*32+g]*w.x;
                ui -= Smh[(a-1)*32+g]*w.y;
                idx = (idx+step)&31;
            }
            Ush[m*32+g] = make_float2(ur,ui);
        }
        __syncthreads();
        // G[m,n], n paired +-: 100 items
        for (int e=t; e<100; e+=256){
            int m = e/10, n = e%10;
            float g1r=0,g1i=0,g2r=0,g2i=0;
            int idx=0;
            #pragma unroll 4
            for (int g=0; g<N32; g++){
                float2 w = ctab[idx];           // (cos gn, sin gn)
                float2 u = Ush[m*32+g];
                float xc=u.x*w.x, ys=u.y*w.y, yc=u.y*w.x, xs=u.x*w.y;
                g1r += xc+ys; g1i += yc-xs;     // e^{-ign}
                g2r += xc-ys; g2i += yc+xs;     // e^{+ign}
                idx = (idx+n)&31;
            }
            Gsh[m*MR2 + 9+n] = make_float2(g1r,g1i);
            if (n) Gsh[m*MR2 + 9-n] = make_float2(g2r,g2i);
        }
        __syncthreads();
        // X2 accumulate in registers
        {
            float qk = g_qw16[k];
            const float* dk = g_d16h + k*NH1;
            int i=0;
            for (int p=t; p<NH2; p+=256){
                float wd = qk*dk[p];
                float2 gg = Gsh[pm[i]*MR2 + pcol[i]];
                axr[i] += wd*gg.x; axi[i] += wd*gg.y; i++;
            }
        }
    }
    __syncthreads();
    {
        float sc = (float)((2.0*PI/32.0)*(2.0*PI/32.0));
        int i=0;
        for (int p=t; p<NH2; p+=256){ X2sh[p]=make_float2(axr[i]*sc, axi[i]*sc); i++; }
    }
    __syncthreads();
    // A[l,m,jn] = sum_jk X2[l,m,jk] dh10[l,jn,jk]
    float2* Aout = g_Aah + (size_t)bc*NH2;
    for (int p=t; p<NH2; p+=256){
        int l,m,jn; unpack_h(p,l,m,jn);
        int w = 2*l+1;
        const float2* X = X2sh + hoff(l) + m*w;
        const float*  dd = g_dh10 + offsq(l) + jn*w;
        float ar=0.0f, ai=0.0f;
        for (int jk=0; jk<w; jk++){ ar += dd[jk]*X[jk].x; ai += dd[jk]*X[jk].y; }
        Aout[p] = make_float2(ar,ai);
    }
}

__global__ void k_wh2(const float* __restrict__ w_so3){
    __shared__ float2 tab[N32];
    int t = threadIdx.x;
    if (t<N32){ double s,c; sincospi(-2.0*t/32.0,&s,&c); tab[t]=make_float2((float)c,(float)s); }
    __syncthreads();
    int tid = blockIdx.x*blockDim.x + t;
    if (tid >= F0*F1*MR2) return;
    int j = tid % MR2; int io = tid / MR2;
    int m = j - 9;
    int inc = m & 31;
    float sr=0.0f, si=0.0f;
    const float* w = w_so3 + io*N32;
    int idx=0;
    #pragma unroll
    for (int p=0;p<N32;p++){
        float2 e = tab[idx];
        sr += w[p]*e.x; si += w[p]*e.y;
        idx=(idx+inc)&31;
    }
    g_Wh2[tid] = make_float2(sr*(1.0f/32.0f), si*(1.0f/32.0f));
}

// Z2 half with 4-way o tiling
__global__ void k_z2(){
    int tid = blockIdx.x*blockDim.x + threadIdx.x;
    if (tid >= BATCH*25*NH2) return;
    int p = tid % NH2; int rest = tid / NH2;
    int oq = rest % 25; int b = rest / 25;
    int l,m,jn; unpack_h(p,l,m,jn);
    int jw = (jn - l) + 9;
    float ar0=0,ai0=0,ar1=0,ai1=0,ar2=0,ai2=0,ar3=0,ai3=0;
    const float2* A = g_Aah + (size_t)b*F0*NH2 + p;
    const float2* W = g_Wh2 + oq*MR2 + jw;
    #pragma unroll 2
    for (int i=0;i<F0;i++){
        float2 a = A[(size_t)i*NH2];
        const float2* Wi = W + (size_t)i*F1*MR2;
        float2 w0 = Wi[0*25*MR2];
        float2 w1 = Wi[1*25*MR2];
        float2 w2 = Wi[2*25*MR2];
        float2 w3 = Wi[3*25*MR2];
        ar0 += a.x*w0.x + a.y*w0.y;  ai0 += a.y*w0.x - a.x*w0.y;
        ar1 += a.x*w1.x + a.y*w1.y;  ai1 += a.y*w1.x - a.x*w1.y;
        ar2 += a.x*w2.x + a.y*w2.y;  ai2 += a.y*w2.x - a.x*w2.y;
        ar3 += a.x*w3.x + a.y*w3.y;  ai3 += a.y*w3.x - a.x*w3.y;
    }
    size_t base = (size_t)(b*F1)*NH2 + p;
    g_Z2h[base + (size_t)(oq   )*NH2] = make_float2(ar0,ai0);
    g_Z2h[base + (size_t)(oq+25)*NH2] = make_float2(ar1,ai1);
    g_Z2h[base + (size_t)(oq+50)*NH2] = make_float2(ar2,ai2);
    g_Z2h[base + (size_t)(oq+75)*NH2] = make_float2(ar3,ai3);
}

// layer-2 synthesis, half spectrum + twiddle pairs. Block per (b,o).
__global__ void k_syn2(){
    __shared__ float2 Zsh[NH2];
    __shared__ float2 Msh[10*MR2];
    __shared__ float2 Tsh[10*N20];
    __shared__ float2 ctab[N20];
    __shared__ double red[256], red2[256];
    int bo = blockIdx.x;
    int t = threadIdx.x;
    if (t < N20){ double s,c; sincospi(2.0*t/20.0,&s,&c); ctab[t]=make_float2((float)c,(float)s); }
    for (int ph=t; ph<NH2; ph+=256){
        int l,m,jn; unpack_h(ph,l,m,jn);
        float2 z = g_Z2h[(size_t)bo*NH2 + ph];
        float w = (float)(2*l+1);
        Zsh[ph] = make_float2(w*z.x, w*z.y);
    }
    double ls=0.0, ls2=0.0;
    float* hbase = g_h2 + (size_t)bo*8000;
    for (int k=0;k<N20;k++){
        __syncthreads();
        const float* dk = g_d10h + k*NH2;
        for (int e=t; e<10*MR2; e+=256){
            int m=e/MR2, jn=e%MR2;
            int n=jn-9;
            int lmin = max(m, abs(n));
            float ar=0.0f, ai=0.0f;
            int off = hoff(lmin);
            for (int l=lmin; l<L2MAX; l++){
                int idx = off + m*(2*l+1) + (n+l);
                float w = dk[idx];
                float2 z = Zsh[idx];
                ar += w*z.x; ai += w*z.y;
                off += (l+1)*(2*l+1);
            }
            Msh[e] = make_float2(ar,ai);
        }
        __syncthreads();
        // PQ fold: 90 items (m=0..9, n=1..9)
        for (int e=t; e<90; e+=256){
            int m = e/9, n = e%9 + 1;
            float2 Mp = Msh[m*MR2 + 9+n];
            float2 Mm = Msh[m*MR2 + 9-n];
            Msh[m*MR2 + 9+n] = make_float2(Mp.x+Mm.x, Mp.y+Mm.y);
            Msh[m*MR2 + 9-n] = make_float2(Mp.x-Mm.x, Mp.y-Mm.y);
        }
        __syncthreads();
        // T-stage: 110 items (m=0..9, g=0..10), mirror 20-g
        for (int e=t; e<110; e+=256){
            int m = e/11, g = e%11;
            float2 M0 = Msh[m*MR2 + 9];
            float tr1=M0.x, ti1=M0.y, tr2=M0.x, ti2=M0.y;
            int idx = g, step = g;
            #pragma unroll
            for (int n=1;n<10;n++){
                float2 w = ctab[idx];
                float2 P = Msh[m*MR2 + 9+n];
                float2 Q = Msh[m*MR2 + 9-n];
                float pcx = P.x*w.x, pcy = P.y*w.x;
                float qsx = Q.x*w.y, qsy = Q.y*w.y;
                tr1 += pcx - qsy; ti1 += pcy + qsx;
                tr2 += pcx + qsy; ti2 += pcy - qsx;
                idx += step; if (idx>=20) idx-=20;
            }
            float sc = (m>0) ? 2.0f : 1.0f;
            Tsh[m*N20+g] = make_float2(sc*tr1, sc*ti1);
            if (g!=0 && g!=10) Tsh[m*N20+20-g] = make_float2(sc*tr2, sc*ti2);
        }
        __syncthreads();
        // H-stage: 220 items (a=0..10, g=0..19), mirror 20-a
        float* hout = hbase + k*400;
        for (int e=t; e<220; e+=256){
            int a = e/20, g = e%20;
            float acc1 = Tsh[g].x, acc2 = acc1;
            int idx = a, step = a;
            #pragma unroll
            for (int m=1;m<10;m++){
                float2 w = ctab[idx];
                float2 tv = Tsh[m*N20+g];
                float p1 = tv.x*w.x, p2 = tv.y*w.y;
                acc1 += p1 - p2;
                acc2 += p1 + p2;
                idx += step; if (idx>=20) idx-=20;
            }
            hout[a*20+g] = acc1;
            ls += acc1; ls2 += (double)acc1*acc1;
            if (a!=0 && a!=10){
                hout[(20-a)*20+g] = acc2;
                ls += acc2; ls2 += (double)acc2*acc2;
            }
        }
    }
    red[t]=ls; red2[t]=ls2; __syncthreads();
    for (int st=128; st>0; st>>=1){ if (t<st){ red[t]+=red[t+st]; red2[t]+=red2[t+st]; } __syncthreads(); }
    if (t==0) g_s2p[bo] = make_double2(red[0], red2[0]);
}

__global__ void k_bn2fin(const float* __restrict__ gw, const float* __restrict__ gb){
    int o = blockIdx.x; int t = threadIdx.x;
    double s=0.0, s2=0.0;
    if (t < BATCH){ double2 p = g_s2p[t*F1+o]; s=p.x; s2=p.y; }
    for (int st=4; st>0; st>>=1){
        s  += __shfl_down_sync(0xffffffffu, s,  st);
        s2 += __shfl_down_sync(0xffffffffu, s2, st);
    }
    if (t==0){
        double N = (double)BATCH*8000.0;
        double mu = s/N;
        double var = s2/N - mu*mu;
        float a = gw[o] * (float)rsqrt(var + 1e-5);
        g_bn2a[o]=a; g_bn2bv[o]= gb[o] - (float)mu * a;
    }
}

__global__ void k_integrate(){
    int bf = blockIdx.x;
    int f = bf % F1;
    int t = threadIdx.x;
    float a = g_bn2a[f], bb = g_bn2bv[f];
    double s = 0.0;
    const float* h = g_h2 + (size_t)bf*8000;
    for (int idx=t; idx<8000; idx+=256){
        int k = idx/400;
        float v = h[idx]*a + bb;
        v = v>0.0f ? v : 0.0f;
        s += (double)v * (double)g_qw10[k];
    }
    __shared__ double sh[256];
    sh[t]=s; __syncthreads();
    for (int st=128; st>0; st>>=1){ if (t<st) sh[t]+=sh[t+st]; __syncthreads(); }
    if (t==0){
        double sc = (2.0*PI/20.0)*(2.0*PI/20.0);
        g_feat[bf] = (float)(sh[0]*sc);
    }
}

__global__ void k_lin(const float* __restrict__ lw, const float* __restrict__ lb,
                      float* __restrict__ out){
    int tid = blockIdx.x*blockDim.x + threadIdx.x;
    if (tid >= BATCH*NCLS) return;
    int c = tid % NCLS, b = tid / NCLS;
    float acc = lb[c];
    for (int f=0; f<F1; f++) acc += g_feat[b*F1+f]*lw[f*NCLS+c];
    out[tid] = acc;
}

// ================= host =================
extern "C" void kernel_launch(void* const* d_in, const int* in_sizes, int n_in,
                              void* d_out, int out_size){
    const float* x     = (const float*)d_in[0];
    const float* w_s2  = (const float*)d_in[1];
    const float* bn1g  = (const float*)d_in[3];
    const float* bn1b  = (const float*)d_in[4];
    const float* w_so3 = (const float*)d_in[5];
    const float* bn2g  = (const float*)d_in[7];
    const float* bn2b  = (const float*)d_in[8];
    const float* linw  = (const float*)d_in[9];
    const float* linb  = (const float*)d_in[10];
    float* out = (float*)d_out;

    k_setup<<<(TSETUP+255)/256,256>>>();
    k_zero_img<<<(BATCH*NA60*NA60+255)/256,256>>>();
    k_project<<<(BATCH*NPTS+255)/256,256>>>(x);
    k_ga<<<(BATCH*NA60*MR1+255)/256,256>>>();
    k_x1<<<(BATCH*NC1+255)/256,256>>>();
    k_wh1<<<(F0*MR1+255)/256,256>>>(w_s2);
    k_y1<<<(F0*NC1+255)/256,256>>>();
    k_syn1<<<BATCH*F0,256>>>();
    k_bn1fin<<<F0,32>>>(bn1g, bn1b);
    k_g2f<<<BATCH*F0,256>>>();
    k_wh2<<<(F0*F1*MR2+255)/256,256>>>(w_so3);
    k_z2<<<(BATCH*25*NH2+255)/256,256>>>();
    k_syn2<<<BATCH*F1,256>>>();
    k_bn2fin<<<F1,32>>>(bn2g, bn2b);
    k_integrate<<<BATCH*F1,256>>>();
    k_lin<<<(BATCH*NCLS+255)/256,256>>>(linw, linb, out);
}

// round 9
// speedup vs baseline: 3.4346x; 1.0378x over previous
#include <cuda_runtime.h>
#include <math.h>

#define PI 3.14159265358979323846

#define BATCH 8
#define NPTS  1024
#define F0    100
#define F1    100
#define NCLS  40

#define NA60  60
#define L1MAX 16
#define N32   32
#define L2MAX 10
#define N20   20

#define NC1   256
#define NH1   2856   // sum_{l<16} (l+1)(2l+1)
#define NH2   715    // sum_{l<10} (l+1)(2l+1)
#define NSQ2  1330   // sum_{l<10} (2l+1)^2
#define MR1   31
#define MR2   19

__device__ __forceinline__ int offsq(int l){ return l*(4*l*l-1)/3; }
__device__ __forceinline__ int hoff(int l){
    return ((l-1)*l*(2*l-1))/3 + (3*(l-1)*l)/2 + l;
}
__device__ __forceinline__ void unpack_h(int p, int &l, int &m, int &jn){
    l=0; while (p >= (l+1)*(2*l+1)){ p -= (l+1)*(2*l+1); l++; }
    m = p/(2*l+1); jn = p%(2*l+1);
}

// ---------------- scratch ----------------
__device__ float2 g_X1 [BATCH*NC1];
__device__ float2 g_Y1 [F0*NC1];
__device__ float  g_h1 [BATCH*F0*N32*N32*N32];
__device__ float  g_bn1a[F0], g_bn1bv[F0];
__device__ float2 g_Wh2[F0*F1*MR2];
__device__ float2 g_Aah[BATCH*F0*NH2];
__device__ float2 g_Z2h[BATCH*F1*NH2];
__device__ float  g_h2 [BATCH*F1*N20*N20*N20];
__device__ float  g_bn2a[F1], g_bn2bv[F1];
__device__ float  g_feat[BATCH*F1];
__device__ double2 g_s1p[BATCH*F0];
__device__ double2 g_s2p[BATCH*F1];

// ---------------- tables ----------------
__device__ float g_d16h  [N32*NH1];
__device__ float g_d10h  [N20*NH2];
__device__ float g_dh10  [NSQ2];
__device__ float g_dcol30[NA60*NC1];
__device__ float g_dhcol [NC1];
__device__ float g_qw30[NA60], g_qw16[N32], g_qw10[N20];

// ============ Wigner-d ============
__device__ double d_ipow(double x, int n){ double r=1.0; for(int i=0;i<n;i++) r*=x; return r; }

__device__ double d_wig(int l, int mp, int m, double beta, const double* f){
    if (l == 0) return 1.0;
    double cb = cos(0.5*beta), sb = sin(0.5*beta);
    int smin = max(0, m-mp);
    int smax = min(l+m, l-mp);
    double pref = sqrt(f[l+mp]*f[l-mp]*f[l+m]*f[l-m]);
    double term = d_ipow(cb, 2*l+m-mp-2*smin) * d_ipow(sb, mp-m+2*smin)
                / (f[l+m-smin]*f[smin]*f[mp-m+smin]*f[l-mp-smin]);
    if ((mp-m+smin)&1) term = -term;
    double acc = term;
    double r2 = (sb*sb)/(cb*cb);
    for (int s=smin; s<smax; s++){
        term *= -r2 * (double)((l+m-s)*(l-mp-s)) / ((double)(s+1)*(double)(mp-m+s+1));
        acc += term;
    }
    return pref*acc;
}

#define T0c (N32*NH1)
#define T1c (N20*NH2)
#define T2c (NSQ2)
#define T3c (NA60*NC1)
#define T4c (NC1)
#define T5c (112)
#define TSETUP (T0c+T1c+T2c+T3c+T4c+T5c)

// setup: compute only lower-k halves of the beta-indexed tables (mirror in k_pre)
__global__ void k_setup(){
    __shared__ double f[32];
    if (threadIdx.x == 0){ f[0]=1.0; for (int i=1;i<32;i++) f[i]=f[i-1]*(double)i; }
    __syncthreads();
    int tid = blockIdx.x*blockDim.x + threadIdx.x;
    if (tid >= TSETUP) return;
    if (tid < T0c){
        int k = tid/NH1;
        if (k >= 16) return;
        int p = tid%NH1;
        int l,m,jn; unpack_h(p,l,m,jn);
        double beta = PI*(2*k+1)/64.0;
        g_d16h[tid] = (float)d_wig(l, m, jn-l, beta, f);
        return;
    }
    tid -= T0c;
    if (tid < T1c){
        int k = tid/NH2;
        if (k >= 10) return;
        int p = tid%NH2;
        int l,m,jn; unpack_h(p,l,m,jn);
        double beta = PI*(2*k+1)/40.0;
        g_d10h[tid] = (float)d_wig(l, m, jn-l, beta, f);
        return;
    }
    tid -= T1c;
    if (tid < T2c){
        int p = tid;
        int l=0; while (p >= (2*l+1)*(2*l+1)){ p -= (2*l+1)*(2*l+1); l++; }
        int jm = p/(2*l+1), jn = p%(2*l+1);
        g_dh10[tid] = (float)d_wig(l, jm-l, jn-l, 0.5*PI, f);
        return;
    }
    tid -= T2c;
    if (tid < T3c){
        int k = tid/NC1;
        if (k >= 30) return;
        int p = tid%NC1;
        int l=0; while ((l+1)*(l+1) <= p) l++;
        int jm = p - l*l;
        double beta = PI*(2*k+1)/120.0;
        g_dcol30[tid] = (float)d_wig(l, jm-l, 0, beta, f);
        return;
    }
    tid -= T3c;
    if (tid < T4c){
        int p = tid;
        int l=0; while ((l+1)*(l+1) <= p) l++;
        int jm = p - l*l;
        g_dhcol[tid] = (float)d_wig(l, jm-l, 0, 0.5*PI, f);
        return;
    }
    tid -= T4c;
    {
        int bgrid, k; float* out;
        if (tid < 60){ bgrid=30; out=g_qw30; k=tid; }
        else if (tid < 92){ bgrid=16; out=g_qw16; k=tid-60; }
        else { bgrid=10; out=g_qw10; k=tid-92; }
        double beta = PI*(2*k+1)/(4.0*bgrid);
        double s = 0.0;
        for (int j=0;j<bgrid;j++)
            s += sin((double)(2*k+1)*(2*j+1)*PI/(4.0*bgrid))/(double)(2*j+1);
        out[k] = (float)((2.0/bgrid)*sin(beta)*s);
    }
}

// pre: blocks 0..99 = wh1+y1 (one block per channel o); blocks 100.. = table mirror
#define M0c (16*NH1)
#define M1c (10*NH2)
#define M3c (30*NC1)
#define MTOT (M0c+M1c+M3c)
#define PREGRID (100 + (MTOT+255)/256)

__global__ void k_pre(const float* __restrict__ w_s2){
    int t = threadIdx.x;
    if (blockIdx.x < 100){
        int o = blockIdx.x;
        __shared__ float2 tab[NA60];
        __shared__ float2 wh[MR1];
        if (t < NA60){ double s,c; sincospi(-2.0*t/60.0,&s,&c); tab[t]=make_float2((float)c,(float)s); }
        __syncthreads();
        if (t < MR1){
            int m = t - 15;
            int inc = ((m%60)+60)%60;
            float sr=0.0f, si=0.0f;
            const float* w = w_s2 + o*NA60;
            int idx=0;
            for (int p=0;p<NA60;p++){
                float2 e = tab[idx];
                sr += w[p]*e.x; si += w[p]*e.y;
                idx += inc; if (idx>=60) idx-=60;
            }
            wh[t] = make_float2(sr,si);
        }
        __syncthreads();
        {
            int p = t;  // 256 entries
            int l=0; while ((l+1)*(l+1) <= p) l++;
            int m = (p - l*l) - l;
            float d = g_dhcol[p] * (1.0f/60.0f);
            float2 w = wh[m+15];
            g_Y1[o*NC1+p] = make_float2(d*w.x, d*w.y);
        }
        return;
    }
    int idx = (blockIdx.x-100)*256 + t;
    if (idx >= MTOT) return;
    if (idx < M0c){
        int kk = 16 + idx/NH1;
        int p = idx%NH1;
        int l,m,jn; unpack_h(p,l,m,jn);
        float v = g_d16h[(31-kk)*NH1 + p + 2*(l-jn)];
        g_d16h[kk*NH1 + p] = ((l+m)&1) ? -v : v;
        return;
    }
    idx -= M0c;
    if (idx < M1c){
        int kk = 10 + idx/NH2;
        int p = idx%NH2;
        int l,m,jn; unpack_h(p,l,m,jn);
        float v = g_d10h[(19-kk)*NH2 + p + 2*(l-jn)];
        g_d10h[kk*NH2 + p] = ((l+m)&1) ? -v : v;
        return;
    }
    idx -= M1c;
    {
        int kk = 30 + idx/NC1;
        int p = idx%NC1;
        int l=0; while ((l+1)*(l+1) <= p) l++;
        int jm = p - l*l;
        float v = g_dcol30[(59-kk)*NC1 + p];
        g_dcol30[kk*NC1 + p] = (jm&1) ? -v : v;
    }
}

// front: one block per batch. smem image -> project -> Ga -> X1.
__global__ void k_front(const float* __restrict__ x){
    __shared__ float  img[NA60*NA60];
    __shared__ float2 Gas[NA60*MR1];
    __shared__ float2 tab[NA60];
    int b = blockIdx.x;
    int t = threadIdx.x;
    for (int i=t; i<NA60*NA60; i+=256) img[i]=0.0f;
    if (t < NA60){ double s,c; sincospi(-2.0*t/60.0,&s,&c); tab[t]=make_float2((float)c,(float)s); }
    __syncthreads();
    for (int p=t; p<NPTS; p+=256){
        float xx = x[b*3*NPTS + 0*NPTS + p];
        float yy = x[b*3*NPTS + 1*NPTS + p];
        float zz = x[b*3*NPTS + 2*NPTS + p];
        float r  = sqrtf(xx*xx + yy*yy + zz*zz);
        float rc = fmaxf(r, 1e-8f);
        float cz = fminf(fmaxf(zz/rc, -1.0f), 1.0f);
        float beta  = acosf(cz);
        float alpha = atan2f(yy, xx);
        if (alpha < 0.0f) alpha += 2.0f*(float)PI;
        int bi = (int)(beta/(float)PI*60.0f);          bi = min(max(bi,0),59);
        int ai = (int)(alpha/(2.0f*(float)PI)*60.0f);  ai = min(max(ai,0),59);
        atomicMax((int*)&img[bi*NA60+ai], __float_as_int(r));   // values >= 0
    }
    __syncthreads();
    for (int e=t; e<NA60*MR1; e+=256){
        int j = e % MR1, k = e / MR1;
        int m = j - 15;
        int inc = ((m%60)+60)%60;
        float sr=0.0f, si=0.0f;
        const float* row = img + k*NA60;
        int idx=0;
        #pragma unroll 4
        for (int a=0;a<NA60;a++){
            float2 w = tab[idx];
            float v = row[a];
            sr += v*w.x; si += v*w.y;
            idx += inc; if (idx>=60) idx-=60;
        }
        Gas[e] = make_float2(sr,si);
    }
    __syncthreads();
    {
        int p = t;
        int l=0; while ((l+1)*(l+1) <= p) l++;
        int m = (p - l*l) - l;
        float ar=0.0f, ai=0.0f;
        for (int k=0;k<NA60;k++){
            float wd = g_qw30[k]*g_dcol30[k*NC1 + p];
            float2 ga = Gas[k*MR1 + (m+15)];
            ar += wd*ga.x; ai += wd*ga.y;
        }
        float sc = (float)(2.0*PI/60.0);
        g_X1[b*NC1+p] = make_float2(ar*sc, ai*sc);
    }
}

// layer-1 synthesis: half-spectrum + twiddle pairs + Parseval BN stats. Block per (b,o).
__global__ void k_syn1(){
    __shared__ float2 Zv [NH1];
    __shared__ float2 Msh[16*MR1];
    __shared__ float2 Tsh[16*N32];
    __shared__ float2 Xsh[NC1], Ysh[NC1];
    __shared__ float2 ctab[N32];
    __shared__ double red[256], red2[256];
    int bo = blockIdx.x;
    int o = bo % F0, b = bo / F0;
    int t = threadIdx.x;
    for (int i=t;i<NC1;i+=256){ Xsh[i]=g_X1[b*NC1+i]; Ysh[i]=g_Y1[o*NC1+i]; }
    if (t < N32){ double s,c; sincospi(2.0*t/32.0,&s,&c); ctab[t]=make_float2((float)c,(float)s); }
    __syncthreads();
    for (int ph=t; ph<NH1; ph+=256){
        int l,m,jn; unpack_h(ph,l,m,jn);
        float2 xv = Xsh[l*l + m+l];
        float2 yv = Ysh[l*l + jn];
        float w = (float)(2*l+1);
        Zv[ph] = make_float2(w*(xv.x*yv.x + xv.y*yv.y),
                             w*(xv.y*yv.x - xv.x*yv.y));
    }
    double hs=0.0, dsq=0.0;        // Parseval accumulators
    float* hbase = g_h1 + (size_t)bo * 32768;
    for (int k=0;k<N32;k++){
        __syncthreads();
        const float* dk = g_d16h + k*NH1;
        for (int e=t; e<16*MR1; e+=256){
            int m = e / MR1, jn = e % MR1;
            int n = jn-15;
            int lmin = max(m, abs(n));
            float ar=0.0f, ai=0.0f;
            int off = hoff(lmin);
            for (int l=lmin; l<L1MAX; l++){
                int idx = off + m*(2*l+1) + (n+l);
                float w = dk[idx];
                float2 z = Zv[idx];
                ar += w*z.x; ai += w*z.y;
                off += (l+1)*(2*l+1);
            }
            Msh[e] = make_float2(ar, ai);
            float w2 = (m>0) ? 2.0f : 1.0f;
            dsq += (double)(w2*(ar*ar + ai*ai));
            if (e == 15) hs += (double)ar;     // M[m=0,n=0]
        }
        __syncthreads();
        for (int e=t; e<240; e+=256){
            int m = e/15, n = e%15 + 1;
            float2 Mp = Msh[m*MR1 + 15+n];
            float2 Mm = Msh[m*MR1 + 15-n];
            Msh[m*MR1 + 15+n] = make_float2(Mp.x+Mm.x, Mp.y+Mm.y);
            Msh[m*MR1 + 15-n] = make_float2(Mp.x-Mm.x, Mp.y-Mm.y);
        }
        __syncthreads();
        for (int e=t; e<272; e+=256){
            int m = e/17, g = e%17;
            float2 M0 = Msh[m*MR1 + 15];
            float tr1=M0.x, ti1=M0.y, tr2=M0.x, ti2=M0.y;
            int idx = g, step = g;
            #pragma unroll
            for (int n=1;n<16;n++){
                float2 w = ctab[idx];
                float2 P = Msh[m*MR1 + 15+n];
                float2 Q = Msh[m*MR1 + 15-n];
                float pcx = P.x*w.x, pcy = P.y*w.x;
                float qsx = Q.x*w.y, qsy = Q.y*w.y;
                tr1 += pcx - qsy; ti1 += pcy + qsx;
                tr2 += pcx + qsy; ti2 += pcy - qsx;
                idx = (idx+step)&31;
            }
            float sc = (m>0) ? 2.0f : 1.0f;
            Tsh[m*N32+g] = make_float2(sc*tr1, sc*ti1);
            if (g!=0 && g!=16) Tsh[m*N32+32-g] = make_float2(sc*tr2, sc*ti2);
        }
        __syncthreads();
        float* hout = hbase + k*1024;
        for (int e=t; e<544; e+=256){
            int a = e >> 5, g = e & 31;
            float acc1 = Tsh[g].x, acc2 = acc1;
            int idx = a, step = a;
            #pragma unroll
            for (int m=1;m<16;m++){
                float2 w = ctab[idx];
                float2 tv = Tsh[m*N32+g];
                float p1 = tv.x*w.x, p2 = tv.y*w.y;
                acc1 += p1 - p2;
                acc2 += p1 + p2;
                idx = (idx+step)&31;
            }
            hout[a*32+g] = acc1;
            if (a!=0 && a!=16) hout[(32-a)*32+g] = acc2;
        }
    }
    red[t]=hs; red2[t]=dsq; __syncthreads();
    for (int st=128; st>0; st>>=1){ if (t<st){ red[t]+=red[t+st]; red2[t]+=red2[t+st]; } __syncthreads(); }
    if (t==0) g_s1p[bo] = make_double2(1024.0*red[0], 1024.0*red2[0]);
}

// bnw: blocks 0..99 = bn1fin; blocks 100.. = wh2
__global__ void k_bnw(const float* __restrict__ gw, const float* __restrict__ gb,
                      const float* __restrict__ w_so3){
    int t = threadIdx.x;
    if (blockIdx.x < 100){
        int o = blockIdx.x;
        if (t >= 32) return;
        double s=0.0, s2=0.0;
        if (t < BATCH){ double2 p = g_s1p[t*F0+o]; s=p.x; s2=p.y; }
        for (int st=4; st>0; st>>=1){
            s  += __shfl_down_sync(0xffffffffu, s,  st);
            s2 += __shfl_down_sync(0xffffffffu, s2, st);
        }
        if (t==0){
            double N = (double)BATCH*32768.0;
            double mu = s/N;
            double var = s2/N - mu*mu;
            float a = gw[o] * (float)rsqrt(var + 1e-5);
            g_bn1a[o]=a; g_bn1bv[o]= gb[o] - (float)mu * a;
        }
        return;
    }
    __shared__ float2 tab[N32];
    if (t<N32){ double s,c; sincospi(-2.0*t/32.0,&s,&c); tab[t]=make_float2((float)c,(float)s); }
    __syncthreads();
    int tid = (blockIdx.x-100)*256 + t;
    if (tid >= F0*F1*MR2) return;
    int j = tid % MR2; int io = tid / MR2;
    int m = j - 9;
    int inc = m & 31;
    float sr=0.0f, si=0.0f;
    const float* w = w_so3 + io*N32;
    int idx=0;
    #pragma unroll
    for (int p=0;p<N32;p++){
        float2 e = tab[idx];
        sr += w[p]*e.x; si += w[p]*e.y;
        idx=(idx+inc)&31;
    }
    g_Wh2[tid] = make_float2(sr*(1.0f/32.0f), si*(1.0f/32.0f));
}

// fused BN+relu + half fft2 + beta-quadrature + pi/2 contraction. Block per (b,c).
__global__ void k_g2f(){
    __shared__ float  hsh[N32*N32];
    __shared__ float  Sph[15*N32], Smh[15*N32];
    __shared__ float2 Ush[10*N32];
    __shared__ float2 Gsh[10*MR2];
    __shared__ float2 ctab[N32];
    __shared__ float2 X2sh[NH2];
    int bc = blockIdx.x;
    int c = bc % F0;
    int t = threadIdx.x;
    float a1 = g_bn1a[c], b1 = g_bn1bv[c];
    if (t<N32){ double s,cc; sincospi(2.0*t/32.0,&s,&cc); ctab[t]=make_float2((float)cc,(float)s); }
    int pm[3], pcol[3];
    float axr[3]={0,0,0}, axi[3]={0,0,0};
    {
        int i=0;
        for (int p=t; p<NH2; p+=256){
            int l,m,jn; unpack_h(p,l,m,jn);
            pm[i]=m; pcol[i]=jn-l+9; i++;
        }
    }
    const float* hbase = g_h1 + (size_t)bc*32768;
    for (int k=0;k<N32;k++){
        __syncthreads();
        const float* hin = hbase + k*1024;
        for (int i=t;i<1024;i+=256){ float v = hin[i]*a1 + b1; hsh[i] = v>0.0f ? v : 0.0f; }
        __syncthreads();
        for (int e=t; e<480; e+=256){
            int a = e/32 + 1, g = e%32;
            float u = hsh[a*32+g], v = hsh[(32-a)*32+g];
            Sph[(a-1)*32+g] = u+v;
            Smh[(a-1)*32+g] = u-v;
        }
        __syncthreads();
        for (int e=t; e<320; e+=256){
            int m = e/32, g = e%32;
            float h16 = hsh[16*32+g];
            float ur = hsh[g] + ((m&1) ? -h16 : h16);
            float ui = 0.0f;
            int idx = m&31, step = m;
            #pragma unroll
            for (int a=1;a<16;a++){
                float2 w = ctab[idx];
                ur += Sph[(a-1)*32+g]*w.x;
                ui -= Smh[(a-1)*32+g]*w.y;
                idx = (idx+step)&31;
            }
            Ush[m*32+g] = make_float2(ur,ui);
        }
        __syncthreads();
        for (int e=t; e<100; e+=256){
            int m = e/10, n = e%10;
            float g1r=0,g1i=0,g2r=0,g2i=0;
            int idx=0;
            #pragma unroll 4
            for (int g=0; g<N32; g++){
                float2 w = ctab[idx];
                float2 u = Ush[m*32+g];
                float xc=u.x*w.x, ys=u.y*w.y, yc=u.y*w.x, xs=u.x*w.y;
                g1r += xc+ys; g1i += yc-xs;
                g2r += xc-ys; g2i += yc+xs;
                idx = (idx+n)&31;
            }
            Gsh[m*MR2 + 9+n] = make_float2(g1r,g1i);
            if (n) Gsh[m*MR2 + 9-n] = make_float2(g2r,g2i);
        }
        __syncthreads();
        {
            float qk = g_qw16[k];
            const float* dk = g_d16h + k*NH1;
            int i=0;
            for (int p=t; p<NH2; p+=256){
                float wd = qk*dk[p];
                float2 gg = Gsh[pm[i]*MR2 + pcol[i]];
                axr[i] += wd*gg.x; axi[i] += wd*gg.y; i++;
            }
        }
    }
    __syncthreads();
    {
        float sc = (float)((2.0*PI/32.0)*(2.0*PI/32.0));
        int i=0;
        for (int p=t; p<NH2; p+=256){ X2sh[p]=make_float2(axr[i]*sc, axi[i]*sc); i++; }
    }
    __syncthreads();
    float2* Aout = g_Aah + (size_t)bc*NH2;
    for (int p=t; p<NH2; p+=256){
        int l,m,jn; unpack_h(p,l,m,jn);
        int w = 2*l+1;
        const float2* X = X2sh + hoff(l) + m*w;
        const float*  dd = g_dh10 + offsq(l) + jn*w;
        float ar=0.0f, ai=0.0f;
        for (int jk=0; jk<w; jk++){ ar += dd[jk]*X[jk].x; ai += dd[jk]*X[jk].y; }
        Aout[p] = make_float2(ar,ai);
    }
}

// Z2 half with 4-way o tiling
__global__ void k_z2(){
    int tid = blockIdx.x*blockDim.x + threadIdx.x;
    if (tid >= BATCH*25*NH2) return;
    int p = tid % NH2; int rest = tid / NH2;
    int oq = rest % 25; int b = rest / 25;
    int l,m,jn; unpack_h(p,l,m,jn);
    int jw = (jn - l) + 9;
    float ar0=0,ai0=0,ar1=0,ai1=0,ar2=0,ai2=0,ar3=0,ai3=0;
    const float2* A = g_Aah + (size_t)b*F0*NH2 + p;
    const float2* W = g_Wh2 + oq*MR2 + jw;
    #pragma unroll 2
    for (int i=0;i<F0;i++){
        float2 a = A[(size_t)i*NH2];
        const float2* Wi = W + (size_t)i*F1*MR2;
        float2 w0 = Wi[0*25*MR2];
        float2 w1 = Wi[1*25*MR2];
        float2 w2 = Wi[2*25*MR2];
        float2 w3 = Wi[3*25*MR2];
        ar0 += a.x*w0.x + a.y*w0.y;  ai0 += a.y*w0.x - a.x*w0.y;
        ar1 += a.x*w1.x + a.y*w1.y;  ai1 += a.y*w1.x - a.x*w1.y;
        ar2 += a.x*w2.x + a.y*w2.y;  ai2 += a.y*w2.x - a.x*w2.y;
        ar3 += a.x*w3.x + a.y*w3.y;  ai3 += a.y*w3.x - a.x*w3.y;
    }
    size_t base = (size_t)(b*F1)*NH2 + p;
    g_Z2h[base + (size_t)(oq   )*NH2] = make_float2(ar0,ai0);
    g_Z2h[base + (size_t)(oq+25)*NH2] = make_float2(ar1,ai1);
    g_Z2h[base + (size_t)(oq+50)*NH2] = make_float2(ar2,ai2);
    g_Z2h[base + (size_t)(oq+75)*NH2] = make_float2(ar3,ai3);
}

// layer-2 synthesis + Parseval stats. Block per (b,o).
__global__ void k_syn2(){
    __shared__ float2 Zsh[NH2];
    __shared__ float2 Msh[10*MR2];
    __shared__ float2 Tsh[10*N20];
    __shared__ float2 ctab[N20];
    __shared__ double red[256], red2[256];
    int bo = blockIdx.x;
    int t = threadIdx.x;
    if (t < N20){ double s,c; sincospi(2.0*t/20.0,&s,&c); ctab[t]=make_float2((float)c,(float)s); }
    for (int ph=t; ph<NH2; ph+=256){
        int l,m,jn; unpack_h(ph,l,m,jn);
        float2 z = g_Z2h[(size_t)bo*NH2 + ph];
        float w = (float)(2*l+1);
        Zsh[ph] = make_float2(w*z.x, w*z.y);
    }
    double hs=0.0, dsq=0.0;
    float* hbase = g_h2 + (size_t)bo*8000;
    for (int k=0;k<N20;k++){
        __syncthreads();
        const float* dk = g_d10h + k*NH2;
        for (int e=t; e<10*MR2; e+=256){
            int m=e/MR2, jn=e%MR2;
            int n=jn-9;
            int lmin = max(m, abs(n));
            float ar=0.0f, ai=0.0f;
            int off = hoff(lmin);
            for (int l=lmin; l<L2MAX; l++){
                int idx = off + m*(2*l+1) + (n+l);
                float w = dk[idx];
                float2 z = Zsh[idx];
                ar += w*z.x; ai += w*z.y;
                off += (l+1)*(2*l+1);
            }
            Msh[e] = make_float2(ar,ai);
            float w2 = (m>0) ? 2.0f : 1.0f;
            dsq += (double)(w2*(ar*ar + ai*ai));
            if (e == 9) hs += (double)ar;     // M[m=0,n=0]
        }
        __syncthreads();
        for (int e=t; e<90; e+=256){
            int m = e/9, n = e%9 + 1;
            float2 Mp = Msh[m*MR2 + 9+n];
            float2 Mm = Msh[m*MR2 + 9-n];
            Msh[m*MR2 + 9+n] = make_float2(Mp.x+Mm.x, Mp.y+Mm.y);
            Msh[m*MR2 + 9-n] = make_float2(Mp.x-Mm.x, Mp.y-Mm.y);
        }
        __syncthreads();
        for (int e=t; e<110; e+=256){
            int m = e/11, g = e%11;
            float2 M0 = Msh[m*MR2 + 9];
            float tr1=M0.x, ti1=M0.y, tr2=M0.x, ti2=M0.y;
            int idx = g, step = g;
            #pragma unroll
            for (int n=1;n<10;n++){
                float2 w = ctab[idx];
                float2 P = Msh[m*MR2 + 9+n];
                float2 Q = Msh[m*MR2 + 9-n];
                float pcx = P.x*w.x, pcy = P.y*w.x;
                float qsx = Q.x*w.y, qsy = Q.y*w.y;
                tr1 += pcx - qsy; ti1 += pcy + qsx;
                tr2 += pcx + qsy; ti2 += pcy - qsx;
                idx += step; if (idx>=20) idx-=20;
            }
            float sc = (m>0) ? 2.0f : 1.0f;
            Tsh[m*N20+g] = make_float2(sc*tr1, sc*ti1);
            if (g!=0 && g!=10) Tsh[m*N20+20-g] = make_float2(sc*tr2, sc*ti2);
        }
        __syncthreads();
        float* hout = hbase + k*400;
        for (int e=t; e<220; e+=256){
            int a = e/20, g = e%20;
            float acc1 = Tsh[g].x, acc2 = acc1;
            int idx = a, step = a;
            #pragma unroll
            for (int m=1;m<10;m++){
                float2 w = ctab[idx];
                float2 tv = Tsh[m*N20+g];
                float p1 = tv.x*w.x, p2 = tv.y*w.y;
                acc1 += p1 - p2;
                acc2 += p1 + p2;
                idx += step; if (idx>=20) idx-=20;
            }
            hout[a*20+g] = acc1;
            if (a!=0 && a!=10) hout[(20-a)*20+g] = acc2;
        }
    }
    red[t]=hs; red2[t]=dsq; __syncthreads();
    for (int st=128; st>0; st>>=1){ if (t<st){ red[t]+=red[t+st]; red2[t]+=red2[t+st]; } __syncthreads(); }
    if (t==0) g_s2p[bo] = make_double2(400.0*red[0], 400.0*red2[0]);
}

__global__ void k_bn2fin(const float* __restrict__ gw, const float* __restrict__ gb){
    int o = blockIdx.x; int t = threadIdx.x;
    double s=0.0, s2=0.0;
    if (t < BATCH){ double2 p = g_s2p[t*F1+o]; s=p.x; s2=p.y; }
    for (int st=4; st>0; st>>=1){
        s  += __shfl_down_sync(0xffffffffu, s,  st);
        s2 += __shfl_down_sync(0xffffffffu, s2, st);
    }
    if (t==0){
        double N = (double)BATCH*8000.0;
        double mu = s/N;
        double var = s2/N - mu*mu;
        float a = gw[o] * (float)rsqrt(var + 1e-5);
        g_bn2a[o]=a; g_bn2bv[o]= gb[o] - (float)mu * a;
    }
}

__global__ void k_integrate(){
    int bf = blockIdx.x;
    int f = bf % F1;
    int t = threadIdx.x;
    float a = g_bn2a[f], bb = g_bn2bv[f];
    double s = 0.0;
    const float* h = g_h2 + (size_t)bf*8000;
    for (int idx=t; idx<8000; idx+=256){
        int k = idx/400;
        float v = h[idx]*a + bb;
        v = v>0.0f ? v : 0.0f;
        s += (double)v * (double)g_qw10[k];
    }
    __shared__ double sh[256];
    sh[t]=s; __syncthreads();
    for (int st=128; st>0; st>>=1){ if (t<st) sh[t]+=sh[t+st]; __syncthreads(); }
    if (t==0){
        double sc = (2.0*PI/20.0)*(2.0*PI/20.0);
        g_feat[bf] = (float)(sh[0]*sc);
    }
}

__global__ void k_lin(const float* __restrict__ lw, const float* __restrict__ lb,
                      float* __restrict__ out){
    int tid = blockIdx.x*blockDim.x + threadIdx.x;
    if (tid >= BATCH*NCLS) return;
    int c = tid % NCLS, b = tid / NCLS;
    float acc = lb[c];
    for (int f=0; f<F1; f++) acc += g_feat[b*F1+f]*lw[f*NCLS+c];
    out[tid] = acc;
}

// ================= host =================
extern "C" void kernel_launch(void* const* d_in, const int* in_sizes, int n_in,
                              void* d_out, int out_size){
    const float* x     = (const float*)d_in[0];
    const float* w_s2  = (const float*)d_in[1];
    const float* bn1g  = (const float*)d_in[3];
    const float* bn1b  = (const float*)d_in[4];
    const float* w_so3 = (const float*)d_in[5];
    const float* bn2g  = (const float*)d_in[7];
    const float* bn2b  = (const float*)d_in[8];
    const float* linw  = (const float*)d_in[9];
    const float* linb  = (const float*)d_in[10];
    float* out = (float*)d_out;

    k_setup<<<(TSETUP+255)/256,256>>>();                       // 1
    k_pre<<<PREGRID,256>>>(w_s2);                              // 2
    k_front<<<BATCH,256>>>(x);                                 // 3
    k_syn1<<<BATCH*F0,256>>>();                                // 4  <- profiled
    k_bnw<<<100 + (F0*F1*MR2+255)/256,256>>>(bn1g,bn1b,w_so3); // 5
    k_g2f<<<BATCH*F0,256>>>();                                 // 6
    k_z2<<<(BATCH*25*NH2+255)/256,256>>>();                    // 7
    k_syn2<<<BATCH*F1,256>>>();                                // 8
    k_bn2fin<<<F1,32>>>(bn2g, bn2b);                           // 9
    k_integrate<<<BATCH*F1,256>>>();                           // 10
    k_lin<<<(BATCH*NCLS+255)/256,256>>>(linw, linb, out);      // 11
}